// round 14
// baseline (speedup 1.0000x reference)
#include <cuda_runtime.h>
#include <cuda_bf16.h>
#include <cstdint>
#include <math.h>

#define N_NODES 50000
#define N_EDGES 400000

// ---------------- device scratch ----------------
__device__ float g_agg[(size_t)N_NODES * 64];
__device__ __align__(128) unsigned char g_wimg[778240];

#define EDGE_UNITS 74
#define NODE_UNITS 33
#define NODE_BASE  540672u
#define BLK 256

// dynamic smem layout (edge)
#define E_SW    0u
#define E_SXHI  32768u
#define E_SXLO  49152u
#define E_SEO   65536u
#define E_SBAR  81920u
#define E_SSRC  81984u
#define E_SBYT  82280u
#define E_SIDX  82432u
#define E_SMEM  83200u
// dynamic smem layout (node)
#define N_SW    0u
#define N_SXHI  32768u
#define N_SXLO  49152u
#define N_SBAR  65536u
#define N_SSRC  65600u
#define N_SBYT  65736u
#define N_SBT   65856u
#define N_SMEM  66176u

// ---------------- low-level helpers ----------------
__device__ __forceinline__ uint32_t smem_u32(const void* p) {
    uint32_t a;
    asm("{ .reg .u64 t; cvta.to.shared.u64 t, %1; cvt.u32.u64 %0, t; }" : "=r"(a) : "l"(p));
    return a;
}
#define MBAR_INIT(a, c) \
    asm volatile("mbarrier.init.shared.b64 [%0], %1;" :: "r"(a), "r"(c) : "memory")
#define MBAR_EXPECT_TX(a, b) \
    asm volatile("mbarrier.arrive.expect_tx.shared.b64 _, [%0], %1;" :: "r"(a), "r"(b) : "memory")

__device__ __forceinline__ void mbar_wait(uint32_t mbar, uint32_t parity) {
    uint32_t done;
    asm volatile(
        "{\n\t.reg .pred p;\n\t"
        "mbarrier.try_wait.parity.acquire.cta.shared::cta.b64 p, [%1], %2;\n\t"
        "selp.b32 %0, 1, 0, p;\n\t}"
        : "=r"(done) : "r"(mbar), "r"(parity) : "memory");
    if (!done) {
        asm volatile(
            "{\n\t.reg .pred P1;\n\t"
            "WL_%=:\n\t"
            "mbarrier.try_wait.parity.acquire.cta.shared::cta.b64 P1, [%0], %1, 0x989680;\n\t"
            "@P1 bra.uni WD_%=;\n\t"
            "bra.uni WL_%=;\n\t"
            "WD_%=:\n\t}"
            :: "r"(mbar), "r"(parity) : "memory");
    }
}
__device__ __forceinline__ void bulk_cp(uint32_t dst, const void* src, uint32_t bytes, uint32_t bar) {
    asm volatile(
        "cp.async.bulk.shared::cluster.global.mbarrier::complete_tx::bytes [%0], [%1], %2, [%3];"
        :: "r"(dst), "l"(src), "r"(bytes), "r"(bar) : "memory");
}
__device__ __forceinline__ void ldsm4t(uint32_t* r, uint32_t addr) {
    asm volatile("ldmatrix.sync.aligned.m8n8.x4.trans.shared.b16 {%0,%1,%2,%3}, [%4];"
        : "=r"(r[0]), "=r"(r[1]), "=r"(r[2]), "=r"(r[3]) : "r"(addr));
}
__device__ __forceinline__ void hmma(float* c, const uint32_t* a, uint32_t b0, uint32_t b1) {
    asm volatile("mma.sync.aligned.m16n8k16.row.col.f32.bf16.bf16.f32 "
        "{%0,%1,%2,%3}, {%4,%5,%6,%7}, {%8,%9}, {%0,%1,%2,%3};"
        : "+f"(c[0]), "+f"(c[1]), "+f"(c[2]), "+f"(c[3])
        : "r"(a[0]), "r"(a[1]), "r"(a[2]), "r"(a[3]), "r"(b0), "r"(b1));
}
__device__ __forceinline__ void split2(float a, float b, uint32_t& h, uint32_t& l) {
    __nv_bfloat162 hb = __floats2bfloat162_rn(a, b);
    float ra = a - __bfloat162float(__low2bfloat16(hb));
    float rb = b - __bfloat162float(__high2bfloat16(hb));
    __nv_bfloat162 lb = __floats2bfloat162_rn(ra, rb);
    h = *reinterpret_cast<uint32_t*>(&hb);
    l = *reinterpret_cast<uint32_t*>(&lb);
}
__device__ __forceinline__ void red2(float* addr, float a, float b) {
    asm volatile("red.global.add.v2.f32 [%0], {%1, %2};" :: "l"(addr), "f"(a), "f"(b) : "memory");
}

// ---------------- weight-stream pipeline (bulk DMA, 4-stage ring) ----------------
struct Pipe {
    uint32_t swaddr;
    uint32_t mbar;
    const uint32_t* srcOff;
    const uint16_t* byt;
    const unsigned char* base;
    int nU;
    int u;
    bool leader;
};
__device__ __forceinline__ void pipe_issue(Pipe& p, int v) {
    if (p.leader && v < p.nU) {
        uint32_t s = (uint32_t)(v & 3);
        uint32_t bar = p.mbar + s * 8u;
        uint32_t nb = p.byt[v];
        MBAR_EXPECT_TX(bar, nb);
        bulk_cp(p.swaddr + s * 8192u, p.base + p.srcOff[v], nb, bar);
    }
}
__device__ __forceinline__ uint32_t pipe_acquire(Pipe& p) {
    int u = p.u;
    __syncthreads();
    pipe_issue(p, u + 3);
    mbar_wait(p.mbar + (uint32_t)(u & 3) * 8u, (uint32_t)((u >> 2) & 1));
    p.u = u + 1;
    return p.swaddr + (uint32_t)(u & 3) * 8192u;
}

// ---------------- MMA tile (half-N): warp h covers cols [NT/2*h, NT/2*(h+1)) ----------------
template<int NT>
__device__ __forceinline__ void mma_tile_h(float (*acc)[4], const uint32_t* ah, const uint32_t* al,
                                           uint32_t stage, int lane, int h) {
    const int i = lane & 7, m = lane >> 3;
    const int row = ((m & 1) << 3) + i;
    const uint32_t rowoff = (uint32_t)row * (2 * NT);
    const int gsel = m >> 1;
    constexpr int JP = NT / 32;
#pragma unroll
    for (int j = 0; j < JP; j++) {
        int G = JP * h + j;
        uint32_t ga = stage + rowoff + (uint32_t)((((2 * G + gsel) ^ i)) << 4);
        uint32_t bh[4]; ldsm4t(bh, ga);
        hmma(acc[2 * j],     ah, bh[0], bh[1]);
        hmma(acc[2 * j + 1], ah, bh[2], bh[3]);
        hmma(acc[2 * j],     al, bh[0], bh[1]);
        hmma(acc[2 * j + 1], al, bh[2], bh[3]);
        uint32_t bl[4]; ldsm4t(bl, ga + NT * 32);
        hmma(acc[2 * j],     ah, bl[0], bl[1]);
        hmma(acc[2 * j + 1], ah, bl[2], bl[3]);
    }
}

__device__ __forceinline__ void zero_acc(float (*acc)[4], int nt) {
#pragma unroll
    for (int j = 0; j < 8; j++)
        if (j < nt) { acc[j][0] = 0.f; acc[j][1] = 0.f; acc[j][2] = 0.f; acc[j][3] = 0.f; }
}

// bias+relu+split for warp's 64-col half, exchange A-frag halves with partner warp.
// sXhi/sXlo layout: [warp][panel(4)][lane][4 regs] (uint4 per thread, conflict-free)
__device__ __forceinline__ void epi_exchange(const float (*acc)[4], const float* __restrict__ bias,
                                             uint32_t (*Ahi)[4], uint32_t (*Alo)[4],
                                             int q, int h, int w, int lane,
                                             char* sm, uint32_t xhi_off, uint32_t xlo_off) {
    uint4* Xhi = (uint4*)(sm + xhi_off);
    uint4* Xlo = (uint4*)(sm + xlo_off);
#pragma unroll
    for (int pp = 0; pp < 4; pp++) {
        int g = 4 * h + pp;
        float2 b0 = *(const float2*)(bias + 16 * g + 2 * q);
        float2 b1 = *(const float2*)(bias + 16 * g + 8 + 2 * q);
        float v00 = fmaxf(acc[2 * pp][0] + b0.x, 0.f), v01 = fmaxf(acc[2 * pp][1] + b0.y, 0.f);
        float v10 = fmaxf(acc[2 * pp][2] + b0.x, 0.f), v11 = fmaxf(acc[2 * pp][3] + b0.y, 0.f);
        float v20 = fmaxf(acc[2 * pp + 1][0] + b1.x, 0.f), v21 = fmaxf(acc[2 * pp + 1][1] + b1.y, 0.f);
        float v30 = fmaxf(acc[2 * pp + 1][2] + b1.x, 0.f), v31 = fmaxf(acc[2 * pp + 1][3] + b1.y, 0.f);
        split2(v00, v01, Ahi[g][0], Alo[g][0]);
        split2(v10, v11, Ahi[g][1], Alo[g][1]);
        split2(v20, v21, Ahi[g][2], Alo[g][2]);
        split2(v30, v31, Ahi[g][3], Alo[g][3]);
        int idx = (w * 4 + pp) * 32 + lane;
        Xhi[idx] = make_uint4(Ahi[g][0], Ahi[g][1], Ahi[g][2], Ahi[g][3]);
        Xlo[idx] = make_uint4(Alo[g][0], Alo[g][1], Alo[g][2], Alo[g][3]);
    }
    __syncthreads();
    int wp = w ^ 1, ho = 1 - h;
#pragma unroll
    for (int pp = 0; pp < 4; pp++) {
        int g = 4 * ho + pp;
        int idx = (wp * 4 + pp) * 32 + lane;
        uint4 vh = Xhi[idx], vl = Xlo[idx];
        Ahi[g][0] = vh.x; Ahi[g][1] = vh.y; Ahi[g][2] = vh.z; Ahi[g][3] = vh.w;
        Alo[g][0] = vl.x; Alo[g][1] = vl.y; Alo[g][2] = vl.z; Alo[g][3] = vl.w;
    }
}

// LN stats over 64 cols split across warp pair. bacc = biased acc (warp's 32 cols).
__device__ __forceinline__ void ln_stats_h(float (*bacc)[4], float* sRed,
                                           int q, int w, int rloc,
                                           float& muA, float& rsA, float& muB, float& rsB) {
    float sA = 0.f, sA2 = 0.f, sB = 0.f, sB2 = 0.f;
#pragma unroll
    for (int k = 0; k < 4; k++) {
        float v0 = bacc[k][0], v1 = bacc[k][1], v2 = bacc[k][2], v3 = bacc[k][3];
        sA += v0 + v1; sA2 += v0 * v0 + v1 * v1;
        sB += v2 + v3; sB2 += v2 * v2 + v3 * v3;
    }
#pragma unroll
    for (int o = 1; o < 4; o <<= 1) {
        sA  += __shfl_xor_sync(0xffffffffu, sA, o);
        sA2 += __shfl_xor_sync(0xffffffffu, sA2, o);
        sB  += __shfl_xor_sync(0xffffffffu, sB, o);
        sB2 += __shfl_xor_sync(0xffffffffu, sB2, o);
    }
    if (q == 0) {
        float* dst = sRed + (w * 8 + rloc) * 4;
        dst[0] = sA; dst[1] = sA2; dst[2] = sB; dst[3] = sB2;
    }
    __syncthreads();
    const float* src = sRed + ((w ^ 1) * 8 + rloc) * 4;
    float tA = sA + src[0], tA2 = sA2 + src[1];
    float tB = sB + src[2], tB2 = sB2 + src[3];
    muA = tA * (1.f / 64.f);
    rsA = rsqrtf(fmaxf(tA2 * (1.f / 64.f) - muA * muA, 0.f) + 1e-5f);
    muB = tB * (1.f / 64.f);
    rsB = rsqrtf(fmaxf(tB2 * (1.f / 64.f) - muB * muB, 0.f) + 1e-5f);
}

// ---------------------------------------------------------------------------
// prep kernel (unchanged weight image)
// ---------------------------------------------------------------------------
__global__ void prep_kernel(const float* ew1, const float* ewh, const float* ew2,
                            const float* aw1, const float* awh, const float* aw2,
                            const float* nw1, const float* nwh, const float* nw2)
{
    const int N[12]  = {128,128,128,64,  128,128,128,64,  128,128,128,64};
    const uint32_t BASE[12] = {0,106496,172032,237568, 270336,376832,442368,507904,
                               540672,614400,679936,745472};
    const int CNT[12] = {26624,16384,16384,8192, 26624,16384,16384,8192, 18432,16384,16384,8192};
    const float* SRC[12] = {ew1, ewh, ewh + 16384, ew2, aw1, awh, awh + 16384, aw2,
                            nw1, nwh, nwh + 16384, nw2};

    int idx = blockIdx.x * blockDim.x + threadIdx.x;
    if (idx >= 194560) return;
    int t = 0, accu = 0;
    while (idx >= accu + CNT[t]) { accu += CNT[t]; t++; }
    int loc = idx - accu;
    int n = loc % N[t], k = loc / N[t];
    float v = SRC[t][(size_t)k * N[t] + n];
    __nv_bfloat16 h = __float2bfloat16(v);
    __nv_bfloat16 l = __float2bfloat16(v - __bfloat162float(h));
    uint32_t pb = (uint32_t)N[t] * 32u;
    uint32_t off = BASE[t] + (uint32_t)(k >> 4) * (pb * 2u)
                 + (uint32_t)(k & 15) * (uint32_t)(2 * N[t])
                 + (uint32_t)((((n >> 3) ^ (k & 7))) << 4) + (uint32_t)(n & 7) * 2u;
    *(__nv_bfloat16*)(g_wimg + off) = h;
    *(__nv_bfloat16*)(g_wimg + off + pb) = l;
}

// ---------------------------------------------------------------------------
// edge kernel: 256 threads (8 warps), 64 edges/CTA, 2 CTAs/SM (4 warps/SMSP)
// ---------------------------------------------------------------------------
__device__ __forceinline__ const float* eptr(int c, int row,
    const float* __restrict__ x, const float* __restrict__ ea, const float* __restrict__ u,
    const int* srcs, const int* tgts, const int* ebs, int e0) {
    if (c < 64)  return x  + (size_t)srcs[row] * 64 + c;
    if (c < 128) return x  + (size_t)tgts[row] * 64 + (c - 64);
    if (c < 192) return ea + (size_t)(e0 + row) * 64 + (c - 128);
    return u + (size_t)ebs[row] * 16 + (c - 192);
}

__global__ void __launch_bounds__(BLK, 2) edge_kernel(
    const float* __restrict__ x, const float* __restrict__ eattr,
    const float* __restrict__ u, const int* __restrict__ ei, const int* __restrict__ batch,
    const float* __restrict__ eb1, const float* __restrict__ ebh, const float* __restrict__ eb2,
    const float* __restrict__ eg,  const float* __restrict__ ebt,
    const float* __restrict__ ab1, const float* __restrict__ abh, const float* __restrict__ ab2,
    const float* __restrict__ ag,  const float* __restrict__ abt)
{
    extern __shared__ __align__(128) char sm[];
    uint32_t* sSrc = (uint32_t*)(sm + E_SSRC);
    uint16_t* sByt = (uint16_t*)(sm + E_SBYT);
    int* sIdx = (int*)(sm + E_SIDX);
    float* sEo = (float*)(sm + E_SEO);
    float* sRed = (float*)(sm + E_SXHI);

    const int tid = threadIdx.x;
    const int lane = tid & 31, w = tid >> 5;
    const int q = lane & 3, rloc = lane >> 2;
    const int pid = w >> 1, h = w & 1;
    const int rA = pid * 16 + rloc, rB = rA + 8;
    const int e0 = blockIdx.x * 64;

    int* srcs = sIdx; int* tgts = sIdx + 64; int* ebs = sIdx + 128;
    if (tid < 64) {
        int s = ei[e0 + tid];
        int t = ei[N_EDGES + e0 + tid];
        srcs[tid] = s; tgts[tid] = t; ebs[tid] = batch[s];
    }
    uint32_t mb = smem_u32(sm + E_SBAR);
    if (tid == 0) {
        for (int s = 0; s < 4; s++) MBAR_INIT(mb + s * 8u, 1);
        const int LU[8]  = {13, 8, 8, 8, 13, 8, 8, 8};
        const int LPB[8] = {4096, 4096, 4096, 2048, 4096, 4096, 4096, 2048};
        uint32_t off = 0; int uu = 0;
        for (int l = 0; l < 8; l++)
            for (int t = 0; t < LU[l]; t++) {
                sSrc[uu] = off; sByt[uu] = (uint16_t)(2 * LPB[l]);
                off += 2 * LPB[l]; uu++;
            }
    }
    __syncthreads();

    Pipe p; p.swaddr = smem_u32(sm + E_SW); p.mbar = mb; p.srcOff = sSrc; p.byt = sByt;
    p.base = g_wimg; p.nU = EDGE_UNITS; p.u = 0; p.leader = (tid == 0);
    pipe_issue(p, 0); pipe_issue(p, 1); pipe_issue(p, 2);

    float acc[8][4];
    uint32_t Ahi[8][4], Alo[8][4];

    const float* B1[2] = {eb1, ab1};
    const float* BH[2] = {ebh, abh};
    const float* B2[2] = {eb2, ab2};

    for (int mlp = 0; mlp < 2; mlp++) {
        zero_acc(acc, 8);
        for (int t = 0; t < 13; t++) {
            uint32_t ah4[4], al4[4];
            int c0 = 16 * t + 2 * q;
            float2 f0 = *(const float2*)eptr(c0,     rA, x, eattr, u, srcs, tgts, ebs, e0);
            float2 f1 = *(const float2*)eptr(c0,     rB, x, eattr, u, srcs, tgts, ebs, e0);
            float2 f2 = *(const float2*)eptr(c0 + 8, rA, x, eattr, u, srcs, tgts, ebs, e0);
            float2 f3 = *(const float2*)eptr(c0 + 8, rB, x, eattr, u, srcs, tgts, ebs, e0);
            split2(f0.x, f0.y, ah4[0], al4[0]);
            split2(f1.x, f1.y, ah4[1], al4[1]);
            split2(f2.x, f2.y, ah4[2], al4[2]);
            split2(f3.x, f3.y, ah4[3], al4[3]);
            uint32_t st = pipe_acquire(p);
            mma_tile_h<128>(acc, ah4, al4, st, lane, h);
        }
        epi_exchange(acc, B1[mlp], Ahi, Alo, q, h, w, lane, sm, E_SXHI, E_SXLO);

        for (int hl = 0; hl < 2; hl++) {
            zero_acc(acc, 8);
            for (int t = 0; t < 8; t++) {
                uint32_t st = pipe_acquire(p);
                mma_tile_h<128>(acc, Ahi[t], Alo[t], st, lane, h);
            }
            epi_exchange(acc, BH[mlp] + hl * 128, Ahi, Alo, q, h, w, lane, sm, E_SXHI, E_SXLO);
        }

        zero_acc(acc, 4);
        for (int t = 0; t < 8; t++) {
            uint32_t st = pipe_acquire(p);
            mma_tile_h<64>(acc, Ahi[t], Alo[t], st, lane, h);
        }
        // bias into bacc (in place), LN across pair
        float bacc[4][4];
#pragma unroll
        for (int jj = 0; jj < 2; jj++) {
            int g = 2 * h + jj;
            float2 b0 = *(const float2*)(B2[mlp] + 16 * g + 2 * q);
            float2 b1 = *(const float2*)(B2[mlp] + 16 * g + 8 + 2 * q);
            bacc[2 * jj][0] = acc[2 * jj][0] + b0.x; bacc[2 * jj][1] = acc[2 * jj][1] + b0.y;
            bacc[2 * jj][2] = acc[2 * jj][2] + b0.x; bacc[2 * jj][3] = acc[2 * jj][3] + b0.y;
            bacc[2 * jj + 1][0] = acc[2 * jj + 1][0] + b1.x; bacc[2 * jj + 1][1] = acc[2 * jj + 1][1] + b1.y;
            bacc[2 * jj + 1][2] = acc[2 * jj + 1][2] + b1.x; bacc[2 * jj + 1][3] = acc[2 * jj + 1][3] + b1.y;
        }
        float muA, rsA, muB, rsB;
        ln_stats_h(bacc, sRed, q, w, rloc, muA, rsA, muB, rsB);

        if (mlp == 0) {
#pragma unroll
            for (int jj = 0; jj < 2; jj++) {
                int g = 2 * h + jj;
#pragma unroll
                for (int s = 0; s < 2; s++) {
                    int c = 16 * g + 8 * s + 2 * q;
                    float2 gm = *(const float2*)(eg + c);
                    float2 bt = *(const float2*)(ebt + c);
                    const float* v = bacc[2 * jj + s];
                    sEo[rA * 64 + c]     = (v[0] - muA) * rsA * gm.x + bt.x;
                    sEo[rA * 64 + c + 1] = (v[1] - muA) * rsA * gm.y + bt.y;
                    sEo[rB * 64 + c]     = (v[2] - muB) * rsB * gm.x + bt.x;
                    sEo[rB * 64 + c + 1] = (v[3] - muB) * rsB * gm.y + bt.y;
                }
            }
            __syncthreads();   // sRed (in sXhi) consumed before next-mlp epilogues reuse buffer
        } else {
            float* rowP_A = g_agg + (size_t)tgts[rA] * 64;
            float* rowP_B = g_agg + (size_t)tgts[rB] * 64;
#pragma unroll
            for (int jj = 0; jj < 2; jj++) {
                int g = 2 * h + jj;
#pragma unroll
                for (int s = 0; s < 2; s++) {
                    int c = 16 * g + 8 * s + 2 * q;
                    float2 gm = *(const float2*)(ag + c);
                    float2 bt = *(const float2*)(abt + c);
                    const float* v = bacc[2 * jj + s];
                    float a0 = (v[0] - muA) * rsA * gm.x + bt.x;
                    float a1 = (v[1] - muA) * rsA * gm.y + bt.y;
                    float a2 = (v[2] - muB) * rsB * gm.x + bt.x;
                    float a3 = (v[3] - muB) * rsB * gm.y + bt.y;
                    red2(rowP_A + c, sEo[rA * 64 + c]     / (1.f + expf(-a0)),
                                     sEo[rA * 64 + c + 1] / (1.f + expf(-a1)));
                    red2(rowP_B + c, sEo[rB * 64 + c]     / (1.f + expf(-a2)),
                                     sEo[rB * 64 + c + 1] / (1.f + expf(-a3)));
                }
            }
        }
    }
}

// ---------------------------------------------------------------------------
// node kernel: 256 threads (8 warps), 64 nodes/CTA, 2 CTAs/SM
// ---------------------------------------------------------------------------
__device__ __forceinline__ const float* nptr(int c, int n, int bt,
    const float* __restrict__ x, const float* __restrict__ u) {
    if (c < 64)  return x + (size_t)n * 64 + c;
    if (c < 128) return g_agg + (size_t)n * 64 + (c - 64);
    return u + (size_t)bt * 16 + (c - 128);
}

__global__ void __launch_bounds__(BLK, 2) node_kernel(
    const float* __restrict__ x, const float* __restrict__ u, const int* __restrict__ batch,
    const float* __restrict__ nb1, const float* __restrict__ nbh, const float* __restrict__ nb2,
    const float* __restrict__ ng,  const float* __restrict__ nbt,
    float* __restrict__ out)
{
    extern __shared__ __align__(128) char sm[];
    uint32_t* sSrc = (uint32_t*)(sm + N_SSRC);
    uint16_t* sByt = (uint16_t*)(sm + N_SBYT);
    int* sBt = (int*)(sm + N_SBT);
    float* sRed = (float*)(sm + N_SXHI);

    const int tid = threadIdx.x;
    const int lane = tid & 31, w = tid >> 5;
    const int q = lane & 3, rloc = lane >> 2;
    const int pid = w >> 1, h = w & 1;
    const int rA = pid * 16 + rloc, rB = rA + 8;
    const int n0 = blockIdx.x * 64;

    if (tid < 64) {
        int n = n0 + tid;
        sBt[tid] = (n < N_NODES) ? batch[n] : 0;
    }
    uint32_t mb = smem_u32(sm + N_SBAR);
    if (tid == 0) {
        for (int s = 0; s < 4; s++) MBAR_INIT(mb + s * 8u, 1);
        const int LU[4]  = {9, 8, 8, 8};
        const int LPB[4] = {4096, 4096, 4096, 2048};
        uint32_t off = 0; int uu = 0;
        for (int l = 0; l < 4; l++)
            for (int t = 0; t < LU[l]; t++) {
                sSrc[uu] = off; sByt[uu] = (uint16_t)(2 * LPB[l]);
                off += 2 * LPB[l]; uu++;
            }
    }
    __syncthreads();

    Pipe p; p.swaddr = smem_u32(sm + N_SW); p.mbar = mb; p.srcOff = sSrc; p.byt = sByt;
    p.base = g_wimg + NODE_BASE; p.nU = NODE_UNITS; p.u = 0; p.leader = (tid == 0);
    pipe_issue(p, 0); pipe_issue(p, 1); pipe_issue(p, 2);

    const int nA = (n0 + rA < N_NODES) ? n0 + rA : N_NODES - 1;
    const int nB = (n0 + rB < N_NODES) ? n0 + rB : N_NODES - 1;
    const int btA = sBt[rA], btB = sBt[rB];

    float acc[8][4];
    uint32_t Ahi[8][4], Alo[8][4];

    zero_acc(acc, 8);
    for (int t = 0; t < 9; t++) {
        uint32_t ah4[4], al4[4];
        int c0 = 16 * t + 2 * q;
        float2 f0 = *(const float2*)nptr(c0,     nA, btA, x, u);
        float2 f1 = *(const float2*)nptr(c0,     nB, btB, x, u);
        float2 f2 = *(const float2*)nptr(c0 + 8, nA, btA, x, u);
        float2 f3 = *(const float2*)nptr(c0 + 8, nB, btB, x, u);
        split2(f0.x, f0.y, ah4[0], al4[0]);
        split2(f1.x, f1.y, ah4[1], al4[1]);
        split2(f2.x, f2.y, ah4[2], al4[2]);
        split2(f3.x, f3.y, ah4[3], al4[3]);
        uint32_t st = pipe_acquire(p);
        mma_tile_h<128>(acc, ah4, al4, st, lane, h);
    }
    epi_exchange(acc, nb1, Ahi, Alo, q, h, w, lane, sm, N_SXHI, N_SXLO);

    for (int hl = 0; hl < 2; hl++) {
        zero_acc(acc, 8);
        for (int t = 0; t < 8; t++) {
            uint32_t st = pipe_acquire(p);
            mma_tile_h<128>(acc, Ahi[t], Alo[t], st, lane, h);
        }
        epi_exchange(acc, nbh + hl * 128, Ahi, Alo, q, h, w, lane, sm, N_SXHI, N_SXLO);
    }

    zero_acc(acc, 4);
    for (int t = 0; t < 8; t++) {
        uint32_t st = pipe_acquire(p);
        mma_tile_h<64>(acc, Ahi[t], Alo[t], st, lane, h);
    }
    float bacc[4][4];
#pragma unroll
    for (int jj = 0; jj < 2; jj++) {
        int g = 2 * h + jj;
        float2 b0 = *(const float2*)(nb2 + 16 * g + 2 * q);
        float2 b1 = *(const float2*)(nb2 + 16 * g + 8 + 2 * q);
        bacc[2 * jj][0] = acc[2 * jj][0] + b0.x; bacc[2 * jj][1] = acc[2 * jj][1] + b0.y;
        bacc[2 * jj][2] = acc[2 * jj][2] + b0.x; bacc[2 * jj][3] = acc[2 * jj][3] + b0.y;
        bacc[2 * jj + 1][0] = acc[2 * jj + 1][0] + b1.x; bacc[2 * jj + 1][1] = acc[2 * jj + 1][1] + b1.y;
        bacc[2 * jj + 1][2] = acc[2 * jj + 1][2] + b1.x; bacc[2 * jj + 1][3] = acc[2 * jj + 1][3] + b1.y;
    }
    float muA, rsA, muB, rsB;
    ln_stats_h(bacc, sRed, q, w, rloc, muA, rsA, muB, rsB);

    const bool vA = (n0 + rA < N_NODES), vB = (n0 + rB < N_NODES);
#pragma unroll
    for (int jj = 0; jj < 2; jj++) {
        int g = 2 * h + jj;
#pragma unroll
        for (int s = 0; s < 2; s++) {
            int c = 16 * g + 8 * s + 2 * q;
            float2 gm = *(const float2*)(ng + c);
            float2 bt = *(const float2*)(nbt + c);
            const float* v = bacc[2 * jj + s];
            if (vA) {
                float2 o; o.x = (v[0] - muA) * rsA * gm.x + bt.x;
                o.y = (v[1] - muA) * rsA * gm.y + bt.y;
                *(float2*)(out + (size_t)(n0 + rA) * 64 + c) = o;
            }
            if (vB) {
                float2 o; o.x = (v[2] - muB) * rsB * gm.x + bt.x;
                o.y = (v[3] - muB) * rsB * gm.y + bt.y;
                *(float2*)(out + (size_t)(n0 + rB) * 64 + c) = o;
            }
        }
    }
}

// ---------------------------------------------------------------------------
extern "C" void kernel_launch(void* const* d_in, const int* in_sizes, int n_in,
                              void* d_out, int out_size)
{
    const float* x     = (const float*)d_in[0];
    const float* eattr = (const float*)d_in[1];
    const float* u     = (const float*)d_in[2];
    const int*   ei    = (const int*)d_in[3];
    const int*   batch = (const int*)d_in[4];
    const float* ew1 = (const float*)d_in[5],  *eb1 = (const float*)d_in[6];
    const float* ewh = (const float*)d_in[7],  *ebh = (const float*)d_in[8];
    const float* ew2 = (const float*)d_in[9],  *eb2 = (const float*)d_in[10];
    const float* eg  = (const float*)d_in[11], *ebt = (const float*)d_in[12];
    const float* aw1 = (const float*)d_in[13], *ab1 = (const float*)d_in[14];
    const float* awh = (const float*)d_in[15], *abh = (const float*)d_in[16];
    const float* aw2 = (const float*)d_in[17], *ab2 = (const float*)d_in[18];
    const float* ag  = (const float*)d_in[19], *abt = (const float*)d_in[20];
    const float* nw1 = (const float*)d_in[21], *nb1 = (const float*)d_in[22];
    const float* nwh = (const float*)d_in[23], *nbh = (const float*)d_in[24];
    const float* nw2 = (const float*)d_in[25], *nb2 = (const float*)d_in[26];
    const float* ng  = (const float*)d_in[27], *nbt = (const float*)d_in[28];
    float* out = (float*)d_out;
    (void)in_sizes; (void)n_in; (void)out_size;

    cudaFuncSetAttribute(edge_kernel, cudaFuncAttributeMaxDynamicSharedMemorySize, E_SMEM);
    cudaFuncSetAttribute(node_kernel, cudaFuncAttributeMaxDynamicSharedMemorySize, N_SMEM);

    void* aggp = nullptr;
    cudaGetSymbolAddress(&aggp, g_agg);
    cudaMemsetAsync(aggp, 0, sizeof(float) * (size_t)N_NODES * 64, 0);

    prep_kernel<<<(194560 + 255) / 256, 256>>>(ew1, ewh, ew2, aw1, awh, aw2, nw1, nwh, nw2);

    edge_kernel<<<N_EDGES / 64, BLK, E_SMEM>>>(
        x, eattr, u, ei, batch,
        eb1, ebh, eb2, eg, ebt,
        ab1, abh, ab2, ag, abt);

    node_kernel<<<(N_NODES + 63) / 64, BLK, N_SMEM>>>(
        x, u, batch, nb1, nbh, nb2, ng, nbt, out);
}

// round 15
// speedup vs baseline: 1.4716x; 1.4716x over previous
#include <cuda_runtime.h>
#include <cuda_bf16.h>
#include <cstdint>
#include <math.h>

#define N_NODES 50000
#define N_EDGES 400000

// ---------------- device scratch ----------------
__device__ float g_agg[(size_t)N_NODES * 64];
__device__ __align__(128) unsigned char g_wimg[778240];

#define EDGE_UNITS 74
#define NODE_UNITS 33
#define NODE_BASE  540672u
#define BLK 128

// ---------------- low-level helpers ----------------
__device__ __forceinline__ uint32_t smem_u32(const void* p) {
    uint32_t a;
    asm("{ .reg .u64 t; cvta.to.shared.u64 t, %1; cvt.u32.u64 %0, t; }" : "=r"(a) : "l"(p));
    return a;
}
#define MBAR_INIT(a, c) \
    asm volatile("mbarrier.init.shared.b64 [%0], %1;" :: "r"(a), "r"(c) : "memory")
#define MBAR_EXPECT_TX(a, b) \
    asm volatile("mbarrier.arrive.expect_tx.shared.b64 _, [%0], %1;" :: "r"(a), "r"(b) : "memory")

__device__ __forceinline__ void mbar_wait(uint32_t mbar, uint32_t parity) {
    uint32_t done;
    asm volatile(
        "{\n\t.reg .pred p;\n\t"
        "mbarrier.try_wait.parity.acquire.cta.shared::cta.b64 p, [%1], %2;\n\t"
        "selp.b32 %0, 1, 0, p;\n\t}"
        : "=r"(done) : "r"(mbar), "r"(parity) : "memory");
    if (!done) {
        asm volatile(
            "{\n\t.reg .pred P1;\n\t"
            "WL_%=:\n\t"
            "mbarrier.try_wait.parity.acquire.cta.shared::cta.b64 P1, [%0], %1, 0x989680;\n\t"
            "@P1 bra.uni WD_%=;\n\t"
            "bra.uni WL_%=;\n\t"
            "WD_%=:\n\t}"
            :: "r"(mbar), "r"(parity) : "memory");
    }
}
__device__ __forceinline__ void bulk_cp(uint32_t dst, const void* src, uint32_t bytes, uint32_t bar) {
    asm volatile(
        "cp.async.bulk.shared::cluster.global.mbarrier::complete_tx::bytes [%0], [%1], %2, [%3];"
        :: "r"(dst), "l"(src), "r"(bytes), "r"(bar) : "memory");
}

__device__ __forceinline__ void ldsm4t(uint32_t* r, uint32_t addr) {
    asm volatile("ldmatrix.sync.aligned.m8n8.x4.trans.shared.b16 {%0,%1,%2,%3}, [%4];"
        : "=r"(r[0]), "=r"(r[1]), "=r"(r[2]), "=r"(r[3]) : "r"(addr));
}
__device__ __forceinline__ void hmma(float* c, const uint32_t* a, uint32_t b0, uint32_t b1) {
    asm volatile("mma.sync.aligned.m16n8k16.row.col.f32.bf16.bf16.f32 "
        "{%0,%1,%2,%3}, {%4,%5,%6,%7}, {%8,%9}, {%0,%1,%2,%3};"
        : "+f"(c[0]), "+f"(c[1]), "+f"(c[2]), "+f"(c[3])
        : "r"(a[0]), "r"(a[1]), "r"(a[2]), "r"(a[3]), "r"(b0), "r"(b1));
}
__device__ __forceinline__ void split2(float a, float b, uint32_t& h, uint32_t& l) {
    __nv_bfloat162 hb = __floats2bfloat162_rn(a, b);
    float ra = a - __bfloat162float(__low2bfloat16(hb));
    float rb = b - __bfloat162float(__high2bfloat16(hb));
    __nv_bfloat162 lb = __floats2bfloat162_rn(ra, rb);
    h = *reinterpret_cast<uint32_t*>(&hb);
    l = *reinterpret_cast<uint32_t*>(&lb);
}
__device__ __forceinline__ void red2(float* addr, float a, float b) {
    asm volatile("red.global.add.v2.f32 [%0], {%1, %2};" :: "l"(addr), "f"(a), "f"(b) : "memory");
}
__device__ __forceinline__ float fast_sigmoid(float a) {
    return __fdividef(1.f, 1.f + __expf(-a));
}

// ---------------- weight-stream pipeline (bulk DMA, 4-stage ring) ----------------
struct Pipe {
    uint32_t swaddr;
    uint32_t mbar;
    const uint32_t* srcOff;
    const uint16_t* byt;
    const unsigned char* base;
    int nU;
    int u;
    bool leader;
};
__device__ __forceinline__ void pipe_issue(Pipe& p, int v) {
    if (p.leader && v < p.nU) {
        uint32_t s = (uint32_t)(v & 3);
        uint32_t bar = p.mbar + s * 8u;
        uint32_t nb = p.byt[v];
        MBAR_EXPECT_TX(bar, nb);
        bulk_cp(p.swaddr + s * 8192u, p.base + p.srcOff[v], nb, bar);
    }
}
__device__ __forceinline__ uint32_t pipe_acquire(Pipe& p) {
    int u = p.u;
    __syncthreads();
    pipe_issue(p, u + 3);
    mbar_wait(p.mbar + (uint32_t)(u & 3) * 8u, (uint32_t)((u >> 2) & 1));
    p.u = u + 1;
    return p.swaddr + (uint32_t)(u & 3) * 8192u;
}

// ---------------- MMA tile: 3-term split, one 16-k panel ----------------
template<int NT>
__device__ __forceinline__ void mma_tile(float (*acc)[4], const uint32_t* ah, const uint32_t* al,
                                         uint32_t stage, int lane) {
    const int i = lane & 7, m = lane >> 3;
    const int row = ((m & 1) << 3) + i;
    const uint32_t rowoff = (uint32_t)row * (2 * NT);
    const int gsel = m >> 1;
#pragma unroll
    for (int j = 0; j < NT / 16; j++) {
        uint32_t ga = stage + rowoff + (uint32_t)((((2 * j + gsel) ^ i)) << 4);
        uint32_t bh[4]; ldsm4t(bh, ga);
        hmma(acc[2 * j],     ah, bh[0], bh[1]);
        hmma(acc[2 * j + 1], ah, bh[2], bh[3]);
        hmma(acc[2 * j],     al, bh[0], bh[1]);
        hmma(acc[2 * j + 1], al, bh[2], bh[3]);
        uint32_t bl[4]; ldsm4t(bl, ga + NT * 32);
        hmma(acc[2 * j],     ah, bl[0], bl[1]);
        hmma(acc[2 * j + 1], ah, bl[2], bl[3]);
    }
}

__device__ __forceinline__ void zero_acc(float (*acc)[4], int nt) {
#pragma unroll
    for (int j = 0; j < 16; j++)
        if (j < nt) { acc[j][0] = 0.f; acc[j][1] = 0.f; acc[j][2] = 0.f; acc[j][3] = 0.f; }
}

__device__ __forceinline__ void epi_relu128(const float (*acc)[4], const float* __restrict__ bias,
                                            uint32_t (*Ahi)[4], uint32_t (*Alo)[4], int q) {
#pragma unroll
    for (int t = 0; t < 8; t++) {
        float2 b0 = *(const float2*)(bias + 16 * t + 2 * q);
        float2 b1 = *(const float2*)(bias + 16 * t + 8 + 2 * q);
        float v00 = fmaxf(acc[2 * t][0] + b0.x, 0.f), v01 = fmaxf(acc[2 * t][1] + b0.y, 0.f);
        float v10 = fmaxf(acc[2 * t][2] + b0.x, 0.f), v11 = fmaxf(acc[2 * t][3] + b0.y, 0.f);
        float v20 = fmaxf(acc[2 * t + 1][0] + b1.x, 0.f), v21 = fmaxf(acc[2 * t + 1][1] + b1.y, 0.f);
        float v30 = fmaxf(acc[2 * t + 1][2] + b1.x, 0.f), v31 = fmaxf(acc[2 * t + 1][3] + b1.y, 0.f);
        split2(v00, v01, Ahi[t][0], Alo[t][0]);
        split2(v10, v11, Ahi[t][1], Alo[t][1]);
        split2(v20, v21, Ahi[t][2], Alo[t][2]);
        split2(v30, v31, Ahi[t][3], Alo[t][3]);
    }
}

__device__ __forceinline__ void ln_stats(const float (*acc)[4], const float* __restrict__ bias, int q,
                                         float (*vv)[4], float& muA, float& rsA, float& muB, float& rsB) {
    float sA = 0.f, sA2 = 0.f, sB = 0.f, sB2 = 0.f;
#pragma unroll
    for (int j = 0; j < 8; j++) {
        float2 b = *(const float2*)(bias + 8 * j + 2 * q);
        float v0 = acc[j][0] + b.x, v1 = acc[j][1] + b.y;
        float v2 = acc[j][2] + b.x, v3 = acc[j][3] + b.y;
        vv[j][0] = v0; vv[j][1] = v1; vv[j][2] = v2; vv[j][3] = v3;
        sA += v0 + v1; sA2 += v0 * v0 + v1 * v1;
        sB += v2 + v3; sB2 += v2 * v2 + v3 * v3;
    }
#pragma unroll
    for (int o = 1; o < 4; o <<= 1) {
        sA  += __shfl_xor_sync(0xffffffffu, sA, o);
        sA2 += __shfl_xor_sync(0xffffffffu, sA2, o);
        sB  += __shfl_xor_sync(0xffffffffu, sB, o);
        sB2 += __shfl_xor_sync(0xffffffffu, sB2, o);
    }
    muA = sA * (1.f / 64.f);
    rsA = rsqrtf(fmaxf(sA2 * (1.f / 64.f) - muA * muA, 0.f) + 1e-5f);
    muB = sB * (1.f / 64.f);
    rsB = rsqrtf(fmaxf(sB2 * (1.f / 64.f) - muB * muB, 0.f) + 1e-5f);
}

// ---------------------------------------------------------------------------
// prep kernel
// ---------------------------------------------------------------------------
__global__ void prep_kernel(const float* ew1, const float* ewh, const float* ew2,
                            const float* aw1, const float* awh, const float* aw2,
                            const float* nw1, const float* nwh, const float* nw2)
{
    const int N[12]  = {128,128,128,64,  128,128,128,64,  128,128,128,64};
    const uint32_t BASE[12] = {0,106496,172032,237568, 270336,376832,442368,507904,
                               540672,614400,679936,745472};
    const int CNT[12] = {26624,16384,16384,8192, 26624,16384,16384,8192, 18432,16384,16384,8192};
    const float* SRC[12] = {ew1, ewh, ewh + 16384, ew2, aw1, awh, awh + 16384, aw2,
                            nw1, nwh, nwh + 16384, nw2};

    int idx = blockIdx.x * blockDim.x + threadIdx.x;
    if (idx >= 194560) return;
    int t = 0, accu = 0;
    while (idx >= accu + CNT[t]) { accu += CNT[t]; t++; }
    int loc = idx - accu;
    int n = loc % N[t], k = loc / N[t];
    float v = SRC[t][(size_t)k * N[t] + n];
    __nv_bfloat16 h = __float2bfloat16(v);
    __nv_bfloat16 l = __float2bfloat16(v - __bfloat162float(h));
    uint32_t pb = (uint32_t)N[t] * 32u;
    uint32_t off = BASE[t] + (uint32_t)(k >> 4) * (pb * 2u)
                 + (uint32_t)(k & 15) * (uint32_t)(2 * N[t])
                 + (uint32_t)((((n >> 3) ^ (k & 7))) << 4) + (uint32_t)(n & 7) * 2u;
    *(__nv_bfloat16*)(g_wimg + off) = h;
    *(__nv_bfloat16*)(g_wimg + off + pb) = l;
}

// ---------------------------------------------------------------------------
// edge kernel: 128 threads, 64 edges/CTA, 3 CTAs/SM
// ---------------------------------------------------------------------------
__device__ __forceinline__ const float* eptr(int c, int row,
    const float* __restrict__ x, const float* __restrict__ ea, const float* __restrict__ u,
    const int* srcs, const int* tgts, const int* ebs, int e0) {
    if (c < 64)  return x  + (size_t)srcs[row] * 64 + c;
    if (c < 128) return x  + (size_t)tgts[row] * 64 + (c - 64);
    if (c < 192) return ea + (size_t)(e0 + row) * 64 + (c - 128);
    return u + (size_t)ebs[row] * 16 + (c - 192);
}

__global__ void __launch_bounds__(BLK, 3) edge_kernel(
    const float* __restrict__ x, const float* __restrict__ eattr,
    const float* __restrict__ u, const int* __restrict__ ei, const int* __restrict__ batch,
    const float* __restrict__ eb1, const float* __restrict__ ebh, const float* __restrict__ eb2,
    const float* __restrict__ eg,  const float* __restrict__ ebt,
    const float* __restrict__ ab1, const float* __restrict__ abh, const float* __restrict__ ab2,
    const float* __restrict__ ag,  const float* __restrict__ abt)
{
    __shared__ __align__(128) unsigned char sW[4 * 8192];
    __shared__ __align__(8) unsigned long long sBar[4];
    __shared__ uint32_t sSrc[EDGE_UNITS];
    __shared__ uint16_t sByt[EDGE_UNITS];
    __shared__ int sIdx[3 * 64];
    __shared__ float sEo[64 * 64];      // e-MLP LN output (edge-major), same-thread RW

    const int tid = threadIdx.x;
    const int lane = tid & 31, warp = tid >> 5;
    const int q = lane & 3, rloc = lane >> 2;
    const int rA = warp * 16 + rloc, rB = rA + 8;
    const int e0 = blockIdx.x * 64;

    int* srcs = sIdx; int* tgts = sIdx + 64; int* ebs = sIdx + 128;
    if (tid < 64) {
        int s = ei[e0 + tid];
        int t = ei[N_EDGES + e0 + tid];
        srcs[tid] = s; tgts[tid] = t; ebs[tid] = batch[s];
    }
    uint32_t mb = smem_u32(sBar);
    if (tid == 0) {
        for (int s = 0; s < 4; s++) MBAR_INIT(mb + s * 8u, 1);
        const int LU[8]  = {13, 8, 8, 8, 13, 8, 8, 8};
        const int LPB[8] = {4096, 4096, 4096, 2048, 4096, 4096, 4096, 2048};
        uint32_t off = 0; int uu = 0;
        for (int l = 0; l < 8; l++)
            for (int t = 0; t < LU[l]; t++) {
                sSrc[uu] = off; sByt[uu] = (uint16_t)(2 * LPB[l]);
                off += 2 * LPB[l]; uu++;
            }
    }
    __syncthreads();

    Pipe p; p.swaddr = smem_u32(sW); p.mbar = mb; p.srcOff = sSrc; p.byt = sByt;
    p.base = g_wimg; p.nU = EDGE_UNITS; p.u = 0; p.leader = (tid == 0);
    pipe_issue(p, 0); pipe_issue(p, 1); pipe_issue(p, 2);

    float acc[16][4];
    uint32_t Ahi[8][4], Alo[8][4];

    const float* B1[2] = {eb1, ab1};
    const float* BH[2] = {ebh, abh};
    const float* B2[2] = {eb2, ab2};

    for (int mlp = 0; mlp < 2; mlp++) {
        zero_acc(acc, 16);
        for (int t = 0; t < 13; t++) {
            uint32_t ah4[4], al4[4];
            int c0 = 16 * t + 2 * q;
            float2 f0 = *(const float2*)eptr(c0,     rA, x, eattr, u, srcs, tgts, ebs, e0);
            float2 f1 = *(const float2*)eptr(c0,     rB, x, eattr, u, srcs, tgts, ebs, e0);
            float2 f2 = *(const float2*)eptr(c0 + 8, rA, x, eattr, u, srcs, tgts, ebs, e0);
            float2 f3 = *(const float2*)eptr(c0 + 8, rB, x, eattr, u, srcs, tgts, ebs, e0);
            split2(f0.x, f0.y, ah4[0], al4[0]);
            split2(f1.x, f1.y, ah4[1], al4[1]);
            split2(f2.x, f2.y, ah4[2], al4[2]);
            split2(f3.x, f3.y, ah4[3], al4[3]);
            uint32_t st = pipe_acquire(p);
            mma_tile<128>(acc, ah4, al4, st, lane);
        }
        epi_relu128(acc, B1[mlp], Ahi, Alo, q);

        for (int hl = 0; hl < 2; hl++) {
            zero_acc(acc, 16);
            for (int t = 0; t < 8; t++) {
                uint32_t st = pipe_acquire(p);
                mma_tile<128>(acc, Ahi[t], Alo[t], st, lane);
            }
            epi_relu128(acc, BH[mlp] + hl * 128, Ahi, Alo, q);
        }

        zero_acc(acc, 8);
        for (int t = 0; t < 8; t++) {
            uint32_t st = pipe_acquire(p);
            mma_tile<64>(acc, Ahi[t], Alo[t], st, lane);
        }
        float vv[8][4], muA, rsA, muB, rsB;
        ln_stats(acc, B2[mlp], q, vv, muA, rsA, muB, rsB);
        if (mlp == 0) {
#pragma unroll
            for (int j = 0; j < 8; j++) {
                int c = 8 * j + 2 * q;
                float2 gm = *(const float2*)(eg + c);
                float2 bt = *(const float2*)(ebt + c);
                sEo[rA * 64 + c]     = (vv[j][0] - muA) * rsA * gm.x + bt.x;
                sEo[rA * 64 + c + 1] = (vv[j][1] - muA) * rsA * gm.y + bt.y;
                sEo[rB * 64 + c]     = (vv[j][2] - muB) * rsB * gm.x + bt.x;
                sEo[rB * 64 + c + 1] = (vv[j][3] - muB) * rsB * gm.y + bt.y;
            }
        } else {
            float* rowP_A = g_agg + (size_t)tgts[rA] * 64;
            float* rowP_B = g_agg + (size_t)tgts[rB] * 64;
#pragma unroll
            for (int j = 0; j < 8; j++) {
                int c = 8 * j + 2 * q;
                float2 gm = *(const float2*)(ag + c);
                float2 bt = *(const float2*)(abt + c);
                float a0 = (vv[j][0] - muA) * rsA * gm.x + bt.x;
                float a1 = (vv[j][1] - muA) * rsA * gm.y + bt.y;
                float a2 = (vv[j][2] - muB) * rsB * gm.x + bt.x;
                float a3 = (vv[j][3] - muB) * rsB * gm.y + bt.y;
                red2(rowP_A + c, sEo[rA * 64 + c]     * fast_sigmoid(a0),
                                 sEo[rA * 64 + c + 1] * fast_sigmoid(a1));
                red2(rowP_B + c, sEo[rB * 64 + c]     * fast_sigmoid(a2),
                                 sEo[rB * 64 + c + 1] * fast_sigmoid(a3));
            }
        }
    }
}

// ---------------------------------------------------------------------------
// node kernel: 128 threads, 64 nodes/CTA, 3 CTAs/SM
// ---------------------------------------------------------------------------
__device__ __forceinline__ const float* nptr(int c, int n, int bt,
    const float* __restrict__ x, const float* __restrict__ u) {
    if (c < 64)  return x + (size_t)n * 64 + c;
    if (c < 128) return g_agg + (size_t)n * 64 + (c - 64);
    return u + (size_t)bt * 16 + (c - 128);
}

__global__ void __launch_bounds__(BLK, 3) node_kernel(
    const float* __restrict__ x, const float* __restrict__ u, const int* __restrict__ batch,
    const float* __restrict__ nb1, const float* __restrict__ nbh, const float* __restrict__ nb2,
    const float* __restrict__ ng,  const float* __restrict__ nbt,
    float* __restrict__ out)
{
    __shared__ __align__(128) unsigned char sW[4 * 8192];
    __shared__ __align__(8) unsigned long long sBar[4];
    __shared__ uint32_t sSrc[NODE_UNITS];
    __shared__ uint16_t sByt[NODE_UNITS];
    __shared__ int sBt[64];

    const int tid = threadIdx.x;
    const int lane = tid & 31, warp = tid >> 5;
    const int q = lane & 3, rloc = lane >> 2;
    const int rA = warp * 16 + rloc, rB = rA + 8;
    const int n0 = blockIdx.x * 64;

    if (tid < 64) {
        int n = n0 + tid;
        sBt[tid] = (n < N_NODES) ? batch[n] : 0;
    }
    uint32_t mb = smem_u32(sBar);
    if (tid == 0) {
        for (int s = 0; s < 4; s++) MBAR_INIT(mb + s * 8u, 1);
        const int LU[4]  = {9, 8, 8, 8};
        const int LPB[4] = {4096, 4096, 4096, 2048};
        uint32_t off = 0; int uu = 0;
        for (int l = 0; l < 4; l++)
            for (int t = 0; t < LU[l]; t++) {
                sSrc[uu] = off; sByt[uu] = (uint16_t)(2 * LPB[l]);
                off += 2 * LPB[l]; uu++;
            }
    }
    __syncthreads();

    Pipe p; p.swaddr = smem_u32(sW); p.mbar = mb; p.srcOff = sSrc; p.byt = sByt;
    p.base = g_wimg + NODE_BASE; p.nU = NODE_UNITS; p.u = 0; p.leader = (tid == 0);
    pipe_issue(p, 0); pipe_issue(p, 1); pipe_issue(p, 2);

    const int nA = (n0 + rA < N_NODES) ? n0 + rA : N_NODES - 1;
    const int nB = (n0 + rB < N_NODES) ? n0 + rB : N_NODES - 1;
    const int btA = sBt[rA], btB = sBt[rB];

    float acc[16][4];
    uint32_t Ahi[8][4], Alo[8][4];

    zero_acc(acc, 16);
    for (int t = 0; t < 9; t++) {
        uint32_t ah4[4], al4[4];
        int c0 = 16 * t + 2 * q;
        float2 f0 = *(const float2*)nptr(c0,     nA, btA, x, u);
        float2 f1 = *(const float2*)nptr(c0,     nB, btB, x, u);
        float2 f2 = *(const float2*)nptr(c0 + 8, nA, btA, x, u);
        float2 f3 = *(const float2*)nptr(c0 + 8, nB, btB, x, u);
        split2(f0.x, f0.y, ah4[0], al4[0]);
        split2(f1.x, f1.y, ah4[1], al4[1]);
        split2(f2.x, f2.y, ah4[2], al4[2]);
        split2(f3.x, f3.y, ah4[3], al4[3]);
        uint32_t st = pipe_acquire(p);
        mma_tile<128>(acc, ah4, al4, st, lane);
    }
    epi_relu128(acc, nb1, Ahi, Alo, q);

    for (int hl = 0; hl < 2; hl++) {
        zero_acc(acc, 16);
        for (int t = 0; t < 8; t++) {
            uint32_t st = pipe_acquire(p);
            mma_tile<128>(acc, Ahi[t], Alo[t], st, lane);
        }
        epi_relu128(acc, nbh + hl * 128, Ahi, Alo, q);
    }

    zero_acc(acc, 8);
    for (int t = 0; t < 8; t++) {
        uint32_t st = pipe_acquire(p);
        mma_tile<64>(acc, Ahi[t], Alo[t], st, lane);
    }
    float vv[8][4], muA, rsA, muB, rsB;
    ln_stats(acc, nb2, q, vv, muA, rsA, muB, rsB);

    const bool vA = (n0 + rA < N_NODES), vB = (n0 + rB < N_NODES);
#pragma unroll
    for (int j = 0; j < 8; j++) {
        int c = 8 * j + 2 * q;
        float2 gm = *(const float2*)(ng + c);
        float2 bt = *(const float2*)(nbt + c);
        if (vA) {
            float2 o; o.x = (vv[j][0] - muA) * rsA * gm.x + bt.x;
            o.y = (vv[j][1] - muA) * rsA * gm.y + bt.y;
            *(float2*)(out + (size_t)(n0 + rA) * 64 + c) = o;
        }
        if (vB) {
            float2 o; o.x = (vv[j][2] - muB) * rsB * gm.x + bt.x;
            o.y = (vv[j][3] - muB) * rsB * gm.y + bt.y;
            *(float2*)(out + (size_t)(n0 + rB) * 64 + c) = o;
        }
    }
}

// ---------------------------------------------------------------------------
extern "C" void kernel_launch(void* const* d_in, const int* in_sizes, int n_in,
                              void* d_out, int out_size)
{
    const float* x     = (const float*)d_in[0];
    const float* eattr = (const float*)d_in[1];
    const float* u     = (const float*)d_in[2];
    const int*   ei    = (const int*)d_in[3];
    const int*   batch = (const int*)d_in[4];
    const float* ew1 = (const float*)d_in[5],  *eb1 = (const float*)d_in[6];
    const float* ewh = (const float*)d_in[7],  *ebh = (const float*)d_in[8];
    const float* ew2 = (const float*)d_in[9],  *eb2 = (const float*)d_in[10];
    const float* eg  = (const float*)d_in[11], *ebt = (const float*)d_in[12];
    const float* aw1 = (const float*)d_in[13], *ab1 = (const float*)d_in[14];
    const float* awh = (const float*)d_in[15], *abh = (const float*)d_in[16];
    const float* aw2 = (const float*)d_in[17], *ab2 = (const float*)d_in[18];
    const float* ag  = (const float*)d_in[19], *abt = (const float*)d_in[20];
    const float* nw1 = (const float*)d_in[21], *nb1 = (const float*)d_in[22];
    const float* nwh = (const float*)d_in[23], *nbh = (const float*)d_in[24];
    const float* nw2 = (const float*)d_in[25], *nb2 = (const float*)d_in[26];
    const float* ng  = (const float*)d_in[27], *nbt = (const float*)d_in[28];
    float* out = (float*)d_out;
    (void)in_sizes; (void)n_in; (void)out_size;

    void* aggp = nullptr;
    cudaGetSymbolAddress(&aggp, g_agg);
    cudaMemsetAsync(aggp, 0, sizeof(float) * (size_t)N_NODES * 64, 0);

    prep_kernel<<<(194560 + 255) / 256, 256>>>(ew1, ewh, ew2, aw1, awh, aw2, nw1, nwh, nw2);

    edge_kernel<<<N_EDGES / 64, BLK>>>(
        x, eattr, u, ei, batch,
        eb1, ebh, eb2, eg, ebt,
        ab1, abh, ab2, ag, abt);

    node_kernel<<<(N_NODES + 63) / 64, BLK>>>(
        x, u, batch, nb1, nbh, nb2, ng, nbt, out);
}

// round 16
// speedup vs baseline: 1.6782x; 1.1404x over previous
#include <cuda_runtime.h>
#include <cuda_fp16.h>
#include <cstdint>
#include <math.h>

#define N_NODES 50000
#define N_EDGES 400000

// ---------------- device scratch ----------------
__device__ float g_agg[(size_t)N_NODES * 64];
__device__ __align__(128) unsigned char g_wimg[778240];

#define EDGE_UNITS 74
#define NODE_UNITS 33
#define NODE_BASE  540672u
#define BLK 128

// ---------------- low-level helpers ----------------
__device__ __forceinline__ uint32_t smem_u32(const void* p) {
    uint32_t a;
    asm("{ .reg .u64 t; cvta.to.shared.u64 t, %1; cvt.u32.u64 %0, t; }" : "=r"(a) : "l"(p));
    return a;
}
#define MBAR_INIT(a, c) \
    asm volatile("mbarrier.init.shared.b64 [%0], %1;" :: "r"(a), "r"(c) : "memory")
#define MBAR_EXPECT_TX(a, b) \
    asm volatile("mbarrier.arrive.expect_tx.shared.b64 _, [%0], %1;" :: "r"(a), "r"(b) : "memory")

__device__ __forceinline__ void mbar_wait(uint32_t mbar, uint32_t parity) {
    uint32_t done;
    asm volatile(
        "{\n\t.reg .pred p;\n\t"
        "mbarrier.try_wait.parity.acquire.cta.shared::cta.b64 p, [%1], %2;\n\t"
        "selp.b32 %0, 1, 0, p;\n\t}"
        : "=r"(done) : "r"(mbar), "r"(parity) : "memory");
    if (!done) {
        asm volatile(
            "{\n\t.reg .pred P1;\n\t"
            "WL_%=:\n\t"
            "mbarrier.try_wait.parity.acquire.cta.shared::cta.b64 P1, [%0], %1, 0x989680;\n\t"
            "@P1 bra.uni WD_%=;\n\t"
            "bra.uni WL_%=;\n\t"
            "WD_%=:\n\t}"
            :: "r"(mbar), "r"(parity) : "memory");
    }
}
__device__ __forceinline__ void bulk_cp(uint32_t dst, const void* src, uint32_t bytes, uint32_t bar) {
    asm volatile(
        "cp.async.bulk.shared::cluster.global.mbarrier::complete_tx::bytes [%0], [%1], %2, [%3];"
        :: "r"(dst), "l"(src), "r"(bytes), "r"(bar) : "memory");
}

__device__ __forceinline__ void ldsm4t(uint32_t* r, uint32_t addr) {
    asm volatile("ldmatrix.sync.aligned.m8n8.x4.trans.shared.b16 {%0,%1,%2,%3}, [%4];"
        : "=r"(r[0]), "=r"(r[1]), "=r"(r[2]), "=r"(r[3]) : "r"(addr));
}
__device__ __forceinline__ void hmma(float* c, const uint32_t* a, uint32_t b0, uint32_t b1) {
    asm volatile("mma.sync.aligned.m16n8k16.row.col.f32.f16.f16.f32 "
        "{%0,%1,%2,%3}, {%4,%5,%6,%7}, {%8,%9}, {%0,%1,%2,%3};"
        : "+f"(c[0]), "+f"(c[1]), "+f"(c[2]), "+f"(c[3])
        : "r"(a[0]), "r"(a[1]), "r"(a[2]), "r"(a[3]), "r"(b0), "r"(b1));
}
__device__ __forceinline__ uint32_t packh2(float a, float b) {
    __half2 h = __floats2half2_rn(a, b);
    return *reinterpret_cast<uint32_t*>(&h);
}
__device__ __forceinline__ void red2(float* addr, float a, float b) {
    asm volatile("red.global.add.v2.f32 [%0], {%1, %2};" :: "l"(addr), "f"(a), "f"(b) : "memory");
}
__device__ __forceinline__ float fast_sigmoid(float a) {
    return __fdividef(1.f, 1.f + __expf(-a));
}

// ---------------- weight-stream pipeline (bulk DMA, 4-stage ring) ----------------
struct Pipe {
    uint32_t swaddr;
    uint32_t mbar;
    const uint32_t* srcOff;
    const uint16_t* byt;
    const unsigned char* base;
    int nU;
    int u;
    bool leader;
};
__device__ __forceinline__ void pipe_issue(Pipe& p, int v) {
    if (p.leader && v < p.nU) {
        uint32_t s = (uint32_t)(v & 3);
        uint32_t bar = p.mbar + s * 8u;
        uint32_t nb = p.byt[v];
        MBAR_EXPECT_TX(bar, nb);
        bulk_cp(p.swaddr + s * 8192u, p.base + p.srcOff[v], nb, bar);
    }
}
__device__ __forceinline__ uint32_t pipe_acquire(Pipe& p) {
    int u = p.u;
    __syncthreads();
    pipe_issue(p, u + 3);
    mbar_wait(p.mbar + (uint32_t)(u & 3) * 8u, (uint32_t)((u >> 2) & 1));
    p.u = u + 1;
    return p.swaddr + (uint32_t)(u & 3) * 8192u;
}

// ---------------- MMA tile: 2-term fp16 (Ah*Bh + Ah*Bl), one 16-k panel ----------------
template<int NT>
__device__ __forceinline__ void mma_tile(float (*acc)[4], const uint32_t* ah,
                                         uint32_t stage, int lane) {
    const int i = lane & 7, m = lane >> 3;
    const int row = ((m & 1) << 3) + i;
    const uint32_t rowoff = (uint32_t)row * (2 * NT);
    const int gsel = m >> 1;
#pragma unroll
    for (int j = 0; j < NT / 16; j++) {
        uint32_t ga = stage + rowoff + (uint32_t)((((2 * j + gsel) ^ i)) << 4);
        uint32_t bh[4]; ldsm4t(bh, ga);
        hmma(acc[2 * j],     ah, bh[0], bh[1]);
        hmma(acc[2 * j + 1], ah, bh[2], bh[3]);
        uint32_t bl[4]; ldsm4t(bl, ga + NT * 32);
        hmma(acc[2 * j],     ah, bl[0], bl[1]);
        hmma(acc[2 * j + 1], ah, bl[2], bl[3]);
    }
}

__device__ __forceinline__ void zero_acc(float (*acc)[4], int nt) {
#pragma unroll
    for (int j = 0; j < 16; j++)
        if (j < nt) { acc[j][0] = 0.f; acc[j][1] = 0.f; acc[j][2] = 0.f; acc[j][3] = 0.f; }
}

__device__ __forceinline__ void epi_relu128(const float (*acc)[4], const float* __restrict__ bias,
                                            uint32_t (*Ahi)[4], int q) {
#pragma unroll
    for (int t = 0; t < 8; t++) {
        float2 b0 = *(const float2*)(bias + 16 * t + 2 * q);
        float2 b1 = *(const float2*)(bias + 16 * t + 8 + 2 * q);
        float v00 = fmaxf(acc[2 * t][0] + b0.x, 0.f), v01 = fmaxf(acc[2 * t][1] + b0.y, 0.f);
        float v10 = fmaxf(acc[2 * t][2] + b0.x, 0.f), v11 = fmaxf(acc[2 * t][3] + b0.y, 0.f);
        float v20 = fmaxf(acc[2 * t + 1][0] + b1.x, 0.f), v21 = fmaxf(acc[2 * t + 1][1] + b1.y, 0.f);
        float v30 = fmaxf(acc[2 * t + 1][2] + b1.x, 0.f), v31 = fmaxf(acc[2 * t + 1][3] + b1.y, 0.f);
        Ahi[t][0] = packh2(v00, v01);
        Ahi[t][1] = packh2(v10, v11);
        Ahi[t][2] = packh2(v20, v21);
        Ahi[t][3] = packh2(v30, v31);
    }
}

__device__ __forceinline__ void ln_stats(const float (*acc)[4], const float* __restrict__ bias, int q,
                                         float (*vv)[4], float& muA, float& rsA, float& muB, float& rsB) {
    float sA = 0.f, sA2 = 0.f, sB = 0.f, sB2 = 0.f;
#pragma unroll
    for (int j = 0; j < 8; j++) {
        float2 b = *(const float2*)(bias + 8 * j + 2 * q);
        float v0 = acc[j][0] + b.x, v1 = acc[j][1] + b.y;
        float v2 = acc[j][2] + b.x, v3 = acc[j][3] + b.y;
        vv[j][0] = v0; vv[j][1] = v1; vv[j][2] = v2; vv[j][3] = v3;
        sA += v0 + v1; sA2 += v0 * v0 + v1 * v1;
        sB += v2 + v3; sB2 += v2 * v2 + v3 * v3;
    }
#pragma unroll
    for (int o = 1; o < 4; o <<= 1) {
        sA  += __shfl_xor_sync(0xffffffffu, sA, o);
        sA2 += __shfl_xor_sync(0xffffffffu, sA2, o);
        sB  += __shfl_xor_sync(0xffffffffu, sB, o);
        sB2 += __shfl_xor_sync(0xffffffffu, sB2, o);
    }
    muA = sA * (1.f / 64.f);
    rsA = rsqrtf(fmaxf(sA2 * (1.f / 64.f) - muA * muA, 0.f) + 1e-5f);
    muB = sB * (1.f / 64.f);
    rsB = rsqrtf(fmaxf(sB2 * (1.f / 64.f) - muB * muB, 0.f) + 1e-5f);
}

// ---------------------------------------------------------------------------
// prep kernel: fp32 weights -> fp16 hi/lo, pre-swizzled, panel-interleaved
// ---------------------------------------------------------------------------
__global__ void prep_kernel(const float* ew1, const float* ewh, const float* ew2,
                            const float* aw1, const float* awh, const float* aw2,
                            const float* nw1, const float* nwh, const float* nw2)
{
    const int N[12]  = {128,128,128,64,  128,128,128,64,  128,128,128,64};
    const uint32_t BASE[12] = {0,106496,172032,237568, 270336,376832,442368,507904,
                               540672,614400,679936,745472};
    const int CNT[12] = {26624,16384,16384,8192, 26624,16384,16384,8192, 18432,16384,16384,8192};
    const float* SRC[12] = {ew1, ewh, ewh + 16384, ew2, aw1, awh, awh + 16384, aw2,
                            nw1, nwh, nwh + 16384, nw2};

    int idx = blockIdx.x * blockDim.x + threadIdx.x;
    if (idx >= 194560) return;
    int t = 0, accu = 0;
    while (idx >= accu + CNT[t]) { accu += CNT[t]; t++; }
    int loc = idx - accu;
    int n = loc % N[t], k = loc / N[t];
    float v = SRC[t][(size_t)k * N[t] + n];
    __half h = __float2half_rn(v);
    __half l = __float2half_rn(v - __half2float(h));
    uint32_t pb = (uint32_t)N[t] * 32u;
    uint32_t off = BASE[t] + (uint32_t)(k >> 4) * (pb * 2u)
                 + (uint32_t)(k & 15) * (uint32_t)(2 * N[t])
                 + (uint32_t)((((n >> 3) ^ (k & 7))) << 4) + (uint32_t)(n & 7) * 2u;
    *(__half*)(g_wimg + off) = h;
    *(__half*)(g_wimg + off + pb) = l;
}

// ---------------------------------------------------------------------------
// edge kernel: 128 threads, 64 edges/CTA, 3 CTAs/SM
// ---------------------------------------------------------------------------
__device__ __forceinline__ const float* eptr(int c, int row,
    const float* __restrict__ x, const float* __restrict__ ea, const float* __restrict__ u,
    const int* srcs, const int* tgts, const int* ebs, int e0) {
    if (c < 64)  return x  + (size_t)srcs[row] * 64 + c;
    if (c < 128) return x  + (size_t)tgts[row] * 64 + (c - 64);
    if (c < 192) return ea + (size_t)(e0 + row) * 64 + (c - 128);
    return u + (size_t)ebs[row] * 16 + (c - 192);
}

__global__ void __launch_bounds__(BLK, 3) edge_kernel(
    const float* __restrict__ x, const float* __restrict__ eattr,
    const float* __restrict__ u, const int* __restrict__ ei, const int* __restrict__ batch,
    const float* __restrict__ eb1, const float* __restrict__ ebh, const float* __restrict__ eb2,
    const float* __restrict__ eg,  const float* __restrict__ ebt,
    const float* __restrict__ ab1, const float* __restrict__ abh, const float* __restrict__ ab2,
    const float* __restrict__ ag,  const float* __restrict__ abt)
{
    __shared__ __align__(128) unsigned char sW[4 * 8192];
    __shared__ __align__(8) unsigned long long sBar[4];
    __shared__ uint32_t sSrc[EDGE_UNITS];
    __shared__ uint16_t sByt[EDGE_UNITS];
    __shared__ int sIdx[3 * 64];
    __shared__ float sEo[64 * 64];      // e-MLP LN output (edge-major), same-thread RW

    const int tid = threadIdx.x;
    const int lane = tid & 31, warp = tid >> 5;
    const int q = lane & 3, rloc = lane >> 2;
    const int rA = warp * 16 + rloc, rB = rA + 8;
    const int e0 = blockIdx.x * 64;

    int* srcs = sIdx; int* tgts = sIdx + 64; int* ebs = sIdx + 128;
    if (tid < 64) {
        int s = ei[e0 + tid];
        int t = ei[N_EDGES + e0 + tid];
        srcs[tid] = s; tgts[tid] = t; ebs[tid] = batch[s];
    }
    uint32_t mb = smem_u32(sBar);
    if (tid == 0) {
        for (int s = 0; s < 4; s++) MBAR_INIT(mb + s * 8u, 1);
        const int LU[8]  = {13, 8, 8, 8, 13, 8, 8, 8};
        const int LPB[8] = {4096, 4096, 4096, 2048, 4096, 4096, 4096, 2048};
        uint32_t off = 0; int uu = 0;
        for (int l = 0; l < 8; l++)
            for (int t = 0; t < LU[l]; t++) {
                sSrc[uu] = off; sByt[uu] = (uint16_t)(2 * LPB[l]);
                off += 2 * LPB[l]; uu++;
            }
    }
    __syncthreads();

    Pipe p; p.swaddr = smem_u32(sW); p.mbar = mb; p.srcOff = sSrc; p.byt = sByt;
    p.base = g_wimg; p.nU = EDGE_UNITS; p.u = 0; p.leader = (tid == 0);
    pipe_issue(p, 0); pipe_issue(p, 1); pipe_issue(p, 2);

    float acc[16][4];
    uint32_t Ahi[8][4];

    const float* B1[2] = {eb1, ab1};
    const float* BH[2] = {ebh, abh};
    const float* B2[2] = {eb2, ab2};

    for (int mlp = 0; mlp < 2; mlp++) {
        zero_acc(acc, 16);
        for (int t = 0; t < 13; t++) {
            uint32_t ah4[4];
            int c0 = 16 * t + 2 * q;
            float2 f0 = *(const float2*)eptr(c0,     rA, x, eattr, u, srcs, tgts, ebs, e0);
            float2 f1 = *(const float2*)eptr(c0,     rB, x, eattr, u, srcs, tgts, ebs, e0);
            float2 f2 = *(const float2*)eptr(c0 + 8, rA, x, eattr, u, srcs, tgts, ebs, e0);
            float2 f3 = *(const float2*)eptr(c0 + 8, rB, x, eattr, u, srcs, tgts, ebs, e0);
            ah4[0] = packh2(f0.x, f0.y);
            ah4[1] = packh2(f1.x, f1.y);
            ah4[2] = packh2(f2.x, f2.y);
            ah4[3] = packh2(f3.x, f3.y);
            uint32_t st = pipe_acquire(p);
            mma_tile<128>(acc, ah4, st, lane);
        }
        epi_relu128(acc, B1[mlp], Ahi, q);

        for (int hl = 0; hl < 2; hl++) {
            zero_acc(acc, 16);
            for (int t = 0; t < 8; t++) {
                uint32_t st = pipe_acquire(p);
                mma_tile<128>(acc, Ahi[t], st, lane);
            }
            epi_relu128(acc, BH[mlp] + hl * 128, Ahi, q);
        }

        zero_acc(acc, 8);
        for (int t = 0; t < 8; t++) {
            uint32_t st = pipe_acquire(p);
            mma_tile<64>(acc, Ahi[t], st, lane);
        }
        float vv[8][4], muA, rsA, muB, rsB;
        ln_stats(acc, B2[mlp], q, vv, muA, rsA, muB, rsB);
        if (mlp == 0) {
#pragma unroll
            for (int j = 0; j < 8; j++) {
                int c = 8 * j + 2 * q;
                float2 gm = *(const float2*)(eg + c);
                float2 bt = *(const float2*)(ebt + c);
                sEo[rA * 64 + c]     = (vv[j][0] - muA) * rsA * gm.x + bt.x;
                sEo[rA * 64 + c + 1] = (vv[j][1] - muA) * rsA * gm.y + bt.y;
                sEo[rB * 64 + c]     = (vv[j][2] - muB) * rsB * gm.x + bt.x;
                sEo[rB * 64 + c + 1] = (vv[j][3] - muB) * rsB * gm.y + bt.y;
            }
        } else {
            float* rowP_A = g_agg + (size_t)tgts[rA] * 64;
            float* rowP_B = g_agg + (size_t)tgts[rB] * 64;
#pragma unroll
            for (int j = 0; j < 8; j++) {
                int c = 8 * j + 2 * q;
                float2 gm = *(const float2*)(ag + c);
                float2 bt = *(const float2*)(abt + c);
                float a0 = (vv[j][0] - muA) * rsA * gm.x + bt.x;
                float a1 = (vv[j][1] - muA) * rsA * gm.y + bt.y;
                float a2 = (vv[j][2] - muB) * rsB * gm.x + bt.x;
                float a3 = (vv[j][3] - muB) * rsB * gm.y + bt.y;
                red2(rowP_A + c, sEo[rA * 64 + c]     * fast_sigmoid(a0),
                                 sEo[rA * 64 + c + 1] * fast_sigmoid(a1));
                red2(rowP_B + c, sEo[rB * 64 + c]     * fast_sigmoid(a2),
                                 sEo[rB * 64 + c + 1] * fast_sigmoid(a3));
            }
        }
    }
}

// ---------------------------------------------------------------------------
// node kernel: 128 threads, 64 nodes/CTA, 3 CTAs/SM
// ---------------------------------------------------------------------------
__device__ __forceinline__ const float* nptr(int c, int n, int bt,
    const float* __restrict__ x, const float* __restrict__ u) {
    if (c < 64)  return x + (size_t)n * 64 + c;
    if (c < 128) return g_agg + (size_t)n * 64 + (c - 64);
    return u + (size_t)bt * 16 + (c - 128);
}

__global__ void __launch_bounds__(BLK, 3) node_kernel(
    const float* __restrict__ x, const float* __restrict__ u, const int* __restrict__ batch,
    const float* __restrict__ nb1, const float* __restrict__ nbh, const float* __restrict__ nb2,
    const float* __restrict__ ng,  const float* __restrict__ nbt,
    float* __restrict__ out)
{
    __shared__ __align__(128) unsigned char sW[4 * 8192];
    __shared__ __align__(8) unsigned long long sBar[4];
    __shared__ uint32_t sSrc[NODE_UNITS];
    __shared__ uint16_t sByt[NODE_UNITS];
    __shared__ int sBt[64];

    const int tid = threadIdx.x;
    const int lane = tid & 31, warp = tid >> 5;
    const int q = lane & 3, rloc = lane >> 2;
    const int rA = warp * 16 + rloc, rB = rA + 8;
    const int n0 = blockIdx.x * 64;

    if (tid < 64) {
        int n = n0 + tid;
        sBt[tid] = (n < N_NODES) ? batch[n] : 0;
    }
    uint32_t mb = smem_u32(sBar);
    if (tid == 0) {
        for (int s = 0; s < 4; s++) MBAR_INIT(mb + s * 8u, 1);
        const int LU[4]  = {9, 8, 8, 8};
        const int LPB[4] = {4096, 4096, 4096, 2048};
        uint32_t off = 0; int uu = 0;
        for (int l = 0; l < 4; l++)
            for (int t = 0; t < LU[l]; t++) {
                sSrc[uu] = off; sByt[uu] = (uint16_t)(2 * LPB[l]);
                off += 2 * LPB[l]; uu++;
            }
    }
    __syncthreads();

    Pipe p; p.swaddr = smem_u32(sW); p.mbar = mb; p.srcOff = sSrc; p.byt = sByt;
    p.base = g_wimg + NODE_BASE; p.nU = NODE_UNITS; p.u = 0; p.leader = (tid == 0);
    pipe_issue(p, 0); pipe_issue(p, 1); pipe_issue(p, 2);

    const int nA = (n0 + rA < N_NODES) ? n0 + rA : N_NODES - 1;
    const int nB = (n0 + rB < N_NODES) ? n0 + rB : N_NODES - 1;
    const int btA = sBt[rA], btB = sBt[rB];

    float acc[16][4];
    uint32_t Ahi[8][4];

    zero_acc(acc, 16);
    for (int t = 0; t < 9; t++) {
        uint32_t ah4[4];
        int c0 = 16 * t + 2 * q;
        float2 f0 = *(const float2*)nptr(c0,     nA, btA, x, u);
        float2 f1 = *(const float2*)nptr(c0,     nB, btB, x, u);
        float2 f2 = *(const float2*)nptr(c0 + 8, nA, btA, x, u);
        float2 f3 = *(const float2*)nptr(c0 + 8, nB, btB, x, u);
        ah4[0] = packh2(f0.x, f0.y);
        ah4[1] = packh2(f1.x, f1.y);
        ah4[2] = packh2(f2.x, f2.y);
        ah4[3] = packh2(f3.x, f3.y);
        uint32_t st = pipe_acquire(p);
        mma_tile<128>(acc, ah4, st, lane);
    }
    epi_relu128(acc, nb1, Ahi, q);

    for (int hl = 0; hl < 2; hl++) {
        zero_acc(acc, 16);
        for (int t = 0; t < 8; t++) {
            uint32_t st = pipe_acquire(p);
            mma_tile<128>(acc, Ahi[t], st, lane);
        }
        epi_relu128(acc, nbh + hl * 128, Ahi, q);
    }

    zero_acc(acc, 8);
    for (int t = 0; t < 8; t++) {
        uint32_t st = pipe_acquire(p);
        mma_tile<64>(acc, Ahi[t], st, lane);
    }
    float vv[8][4], muA, rsA, muB, rsB;
    ln_stats(acc, nb2, q, vv, muA, rsA, muB, rsB);

    const bool vA = (n0 + rA < N_NODES), vB = (n0 + rB < N_NODES);
#pragma unroll
    for (int j = 0; j < 8; j++) {
        int c = 8 * j + 2 * q;
        float2 gm = *(const float2*)(ng + c);
        float2 bt = *(const float2*)(nbt + c);
        if (vA) {
            float2 o; o.x = (vv[j][0] - muA) * rsA * gm.x + bt.x;
            o.y = (vv[j][1] - muA) * rsA * gm.y + bt.y;
            *(float2*)(out + (size_t)(n0 + rA) * 64 + c) = o;
        }
        if (vB) {
            float2 o; o.x = (vv[j][2] - muB) * rsB * gm.x + bt.x;
            o.y = (vv[j][3] - muB) * rsB * gm.y + bt.y;
            *(float2*)(out + (size_t)(n0 + rB) * 64 + c) = o;
        }
    }
}

// ---------------------------------------------------------------------------
extern "C" void kernel_launch(void* const* d_in, const int* in_sizes, int n_in,
                              void* d_out, int out_size)
{
    const float* x     = (const float*)d_in[0];
    const float* eattr = (const float*)d_in[1];
    const float* u     = (const float*)d_in[2];
    const int*   ei    = (const int*)d_in[3];
    const int*   batch = (const int*)d_in[4];
    const float* ew1 = (const float*)d_in[5],  *eb1 = (const float*)d_in[6];
    const float* ewh = (const float*)d_in[7],  *ebh = (const float*)d_in[8];
    const float* ew2 = (const float*)d_in[9],  *eb2 = (const float*)d_in[10];
    const float* eg  = (const float*)d_in[11], *ebt = (const float*)d_in[12];
    const float* aw1 = (const float*)d_in[13], *ab1 = (const float*)d_in[14];
    const float* awh = (const float*)d_in[15], *abh = (const float*)d_in[16];
    const float* aw2 = (const float*)d_in[17], *ab2 = (const float*)d_in[18];
    const float* ag  = (const float*)d_in[19], *abt = (const float*)d_in[20];
    const float* nw1 = (const float*)d_in[21], *nb1 = (const float*)d_in[22];
    const float* nwh = (const float*)d_in[23], *nbh = (const float*)d_in[24];
    const float* nw2 = (const float*)d_in[25], *nb2 = (const float*)d_in[26];
    const float* ng  = (const float*)d_in[27], *nbt = (const float*)d_in[28];
    float* out = (float*)d_out;
    (void)in_sizes; (void)n_in; (void)out_size;

    void* aggp = nullptr;
    cudaGetSymbolAddress(&aggp, g_agg);
    cudaMemsetAsync(aggp, 0, sizeof(float) * (size_t)N_NODES * 64, 0);

    prep_kernel<<<(194560 + 255) / 256, 256>>>(ew1, ewh, ew2, aw1, awh, aw2, nw1, nwh, nw2);

    edge_kernel<<<N_EDGES / 64, BLK>>>(
        x, eattr, u, ei, batch,
        eb1, ebh, eb2, eg, ebt,
        ab1, abh, ab2, ag, abt);

    node_kernel<<<(N_NODES + 63) / 64, BLK>>>(
        x, u, batch, nb1, nbh, nb2, ng, nbt, out);
}

// round 17
// speedup vs baseline: 1.8276x; 1.0890x over previous
#include <cuda_runtime.h>
#include <cuda_fp16.h>
#include <cstdint>
#include <math.h>

#define N_NODES 50000
#define N_EDGES 400000

// ---------------- device scratch ----------------
__device__ float g_agg[(size_t)N_NODES * 64];
__device__ __align__(128) unsigned char g_wimg[778240];

#define EDGE_UNITS 74
#define NODE_UNITS 33
#define NODE_BASE  540672u
#define BLK 128

// ---------------- low-level helpers ----------------
__device__ __forceinline__ uint32_t smem_u32(const void* p) {
    uint32_t a;
    asm("{ .reg .u64 t; cvta.to.shared.u64 t, %1; cvt.u32.u64 %0, t; }" : "=r"(a) : "l"(p));
    return a;
}
#define MBAR_INIT(a, c) \
    asm volatile("mbarrier.init.shared.b64 [%0], %1;" :: "r"(a), "r"(c) : "memory")
#define MBAR_EXPECT_TX(a, b) \
    asm volatile("mbarrier.arrive.expect_tx.shared.b64 _, [%0], %1;" :: "r"(a), "r"(b) : "memory")

__device__ __forceinline__ void mbar_wait(uint32_t mbar, uint32_t parity) {
    uint32_t done;
    asm volatile(
        "{\n\t.reg .pred p;\n\t"
        "mbarrier.try_wait.parity.acquire.cta.shared::cta.b64 p, [%1], %2;\n\t"
        "selp.b32 %0, 1, 0, p;\n\t}"
        : "=r"(done) : "r"(mbar), "r"(parity) : "memory");
    if (!done) {
        asm volatile(
            "{\n\t.reg .pred P1;\n\t"
            "WL_%=:\n\t"
            "mbarrier.try_wait.parity.acquire.cta.shared::cta.b64 P1, [%0], %1, 0x989680;\n\t"
            "@P1 bra.uni WD_%=;\n\t"
            "bra.uni WL_%=;\n\t"
            "WD_%=:\n\t}"
            :: "r"(mbar), "r"(parity) : "memory");
    }
}
__device__ __forceinline__ void bulk_cp(uint32_t dst, const void* src, uint32_t bytes, uint32_t bar) {
    asm volatile(
        "cp.async.bulk.shared::cluster.global.mbarrier::complete_tx::bytes [%0], [%1], %2, [%3];"
        :: "r"(dst), "l"(src), "r"(bytes), "r"(bar) : "memory");
}

__device__ __forceinline__ void ldsm4t(uint32_t* r, uint32_t addr) {
    asm volatile("ldmatrix.sync.aligned.m8n8.x4.trans.shared.b16 {%0,%1,%2,%3}, [%4];"
        : "=r"(r[0]), "=r"(r[1]), "=r"(r[2]), "=r"(r[3]) : "r"(addr));
}
__device__ __forceinline__ void hmma(float* c, const uint32_t* a, uint32_t b0, uint32_t b1) {
    asm volatile("mma.sync.aligned.m16n8k16.row.col.f32.f16.f16.f32 "
        "{%0,%1,%2,%3}, {%4,%5,%6,%7}, {%8,%9}, {%0,%1,%2,%3};"
        : "+f"(c[0]), "+f"(c[1]), "+f"(c[2]), "+f"(c[3])
        : "r"(a[0]), "r"(a[1]), "r"(a[2]), "r"(a[3]), "r"(b0), "r"(b1));
}
__device__ __forceinline__ uint32_t packh2(float a, float b) {
    __half2 h = __floats2half2_rn(a, b);
    return *reinterpret_cast<uint32_t*>(&h);
}
__device__ __forceinline__ void red2(float* addr, float a, float b) {
    asm volatile("red.global.add.v2.f32 [%0], {%1, %2};" :: "l"(addr), "f"(a), "f"(b) : "memory");
}
__device__ __forceinline__ float fast_sigmoid(float a) {
    return __fdividef(1.f, 1.f + __expf(-a));
}

// ---------------- weight-stream pipeline (bulk DMA, 4-stage ring) ----------------
struct Pipe {
    uint32_t swaddr;
    uint32_t mbar;
    const uint32_t* srcOff;
    const uint16_t* byt;
    const unsigned char* base;
    int nU;
    int u;
    bool leader;
};
__device__ __forceinline__ void pipe_issue(Pipe& p, int v) {
    if (p.leader && v < p.nU) {
        uint32_t s = (uint32_t)(v & 3);
        uint32_t bar = p.mbar + s * 8u;
        uint32_t nb = p.byt[v];
        MBAR_EXPECT_TX(bar, nb);
        bulk_cp(p.swaddr + s * 8192u, p.base + p.srcOff[v], nb, bar);
    }
}
__device__ __forceinline__ uint32_t pipe_acquire(Pipe& p) {
    int u = p.u;
    __syncthreads();
    pipe_issue(p, u + 3);
    mbar_wait(p.mbar + (uint32_t)(u & 3) * 8u, (uint32_t)((u >> 2) & 1));
    p.u = u + 1;
    return p.swaddr + (uint32_t)(u & 3) * 8192u;
}

// ---------------- MMA tile: 2-term fp16 (Ah*Bh + Ah*Bl), one 16-k panel ----------------
template<int NT>
__device__ __forceinline__ void mma_tile(float (*acc)[4], const uint32_t* ah,
                                         uint32_t stage, int lane) {
    const int i = lane & 7, m = lane >> 3;
    const int row = ((m & 1) << 3) + i;
    const uint32_t rowoff = (uint32_t)row * (2 * NT);
    const int gsel = m >> 1;
#pragma unroll
    for (int j = 0; j < NT / 16; j++) {
        uint32_t ga = stage + rowoff + (uint32_t)((((2 * j + gsel) ^ i)) << 4);
        uint32_t bh[4]; ldsm4t(bh, ga);
        hmma(acc[2 * j],     ah, bh[0], bh[1]);
        hmma(acc[2 * j + 1], ah, bh[2], bh[3]);
        uint32_t bl[4]; ldsm4t(bl, ga + NT * 32);
        hmma(acc[2 * j],     ah, bl[0], bl[1]);
        hmma(acc[2 * j + 1], ah, bl[2], bl[3]);
    }
}

__device__ __forceinline__ void zero_acc(float (*acc)[4], int nt) {
#pragma unroll
    for (int j = 0; j < 16; j++)
        if (j < nt) { acc[j][0] = 0.f; acc[j][1] = 0.f; acc[j][2] = 0.f; acc[j][3] = 0.f; }
}

__device__ __forceinline__ void epi_relu128(const float (*acc)[4], const float* __restrict__ bias,
                                            uint32_t (*Ahi)[4], int q) {
#pragma unroll
    for (int t = 0; t < 8; t++) {
        float2 b0 = *(const float2*)(bias + 16 * t + 2 * q);
        float2 b1 = *(const float2*)(bias + 16 * t + 8 + 2 * q);
        float v00 = fmaxf(acc[2 * t][0] + b0.x, 0.f), v01 = fmaxf(acc[2 * t][1] + b0.y, 0.f);
        float v10 = fmaxf(acc[2 * t][2] + b0.x, 0.f), v11 = fmaxf(acc[2 * t][3] + b0.y, 0.f);
        float v20 = fmaxf(acc[2 * t + 1][0] + b1.x, 0.f), v21 = fmaxf(acc[2 * t + 1][1] + b1.y, 0.f);
        float v30 = fmaxf(acc[2 * t + 1][2] + b1.x, 0.f), v31 = fmaxf(acc[2 * t + 1][3] + b1.y, 0.f);
        Ahi[t][0] = packh2(v00, v01);
        Ahi[t][1] = packh2(v10, v11);
        Ahi[t][2] = packh2(v20, v21);
        Ahi[t][3] = packh2(v30, v31);
    }
}

__device__ __forceinline__ void ln_stats(const float (*acc)[4], const float* __restrict__ bias, int q,
                                         float (*vv)[4], float& muA, float& rsA, float& muB, float& rsB) {
    float sA = 0.f, sA2 = 0.f, sB = 0.f, sB2 = 0.f;
#pragma unroll
    for (int j = 0; j < 8; j++) {
        float2 b = *(const float2*)(bias + 8 * j + 2 * q);
        float v0 = acc[j][0] + b.x, v1 = acc[j][1] + b.y;
        float v2 = acc[j][2] + b.x, v3 = acc[j][3] + b.y;
        vv[j][0] = v0; vv[j][1] = v1; vv[j][2] = v2; vv[j][3] = v3;
        sA += v0 + v1; sA2 += v0 * v0 + v1 * v1;
        sB += v2 + v3; sB2 += v2 * v2 + v3 * v3;
    }
#pragma unroll
    for (int o = 1; o < 4; o <<= 1) {
        sA  += __shfl_xor_sync(0xffffffffu, sA, o);
        sA2 += __shfl_xor_sync(0xffffffffu, sA2, o);
        sB  += __shfl_xor_sync(0xffffffffu, sB, o);
        sB2 += __shfl_xor_sync(0xffffffffu, sB2, o);
    }
    muA = sA * (1.f / 64.f);
    rsA = rsqrtf(fmaxf(sA2 * (1.f / 64.f) - muA * muA, 0.f) + 1e-5f);
    muB = sB * (1.f / 64.f);
    rsB = rsqrtf(fmaxf(sB2 * (1.f / 64.f) - muB * muB, 0.f) + 1e-5f);
}

// ---------------------------------------------------------------------------
// prep kernel: fp32 weights -> fp16 hi/lo, pre-swizzled, panel-interleaved
// ---------------------------------------------------------------------------
__global__ void prep_kernel(const float* ew1, const float* ewh, const float* ew2,
                            const float* aw1, const float* awh, const float* aw2,
                            const float* nw1, const float* nwh, const float* nw2)
{
    const int N[12]  = {128,128,128,64,  128,128,128,64,  128,128,128,64};
    const uint32_t BASE[12] = {0,106496,172032,237568, 270336,376832,442368,507904,
                               540672,614400,679936,745472};
    const int CNT[12] = {26624,16384,16384,8192, 26624,16384,16384,8192, 18432,16384,16384,8192};
    const float* SRC[12] = {ew1, ewh, ewh + 16384, ew2, aw1, awh, awh + 16384, aw2,
                            nw1, nwh, nwh + 16384, nw2};

    int idx = blockIdx.x * blockDim.x + threadIdx.x;
    if (idx >= 194560) return;
    int t = 0, accu = 0;
    while (idx >= accu + CNT[t]) { accu += CNT[t]; t++; }
    int loc = idx - accu;
    int n = loc % N[t], k = loc / N[t];
    float v = SRC[t][(size_t)k * N[t] + n];
    __half h = __float2half_rn(v);
    __half l = __float2half_rn(v - __half2float(h));
    uint32_t pb = (uint32_t)N[t] * 32u;
    uint32_t off = BASE[t] + (uint32_t)(k >> 4) * (pb * 2u)
                 + (uint32_t)(k & 15) * (uint32_t)(2 * N[t])
                 + (uint32_t)((((n >> 3) ^ (k & 7))) << 4) + (uint32_t)(n & 7) * 2u;
    *(__half*)(g_wimg + off) = h;
    *(__half*)(g_wimg + off + pb) = l;
}

// ---------------------------------------------------------------------------
// edge kernel: 128 threads, 64 edges/CTA, 4 CTAs/SM (4 warps/SMSP)
// ---------------------------------------------------------------------------
__device__ __forceinline__ const float* eptr(int c, int row,
    const float* __restrict__ x, const float* __restrict__ ea, const float* __restrict__ u,
    const int* srcs, const int* tgts, const int* ebs, int e0) {
    if (c < 64)  return x  + (size_t)srcs[row] * 64 + c;
    if (c < 128) return x  + (size_t)tgts[row] * 64 + (c - 64);
    if (c < 192) return ea + (size_t)(e0 + row) * 64 + (c - 128);
    return u + (size_t)ebs[row] * 16 + (c - 192);
}

__global__ void __launch_bounds__(BLK, 4) edge_kernel(
    const float* __restrict__ x, const float* __restrict__ eattr,
    const float* __restrict__ u, const int* __restrict__ ei, const int* __restrict__ batch,
    const float* __restrict__ eb1, const float* __restrict__ ebh, const float* __restrict__ eb2,
    const float* __restrict__ eg,  const float* __restrict__ ebt,
    const float* __restrict__ ab1, const float* __restrict__ abh, const float* __restrict__ ab2,
    const float* __restrict__ ag,  const float* __restrict__ abt)
{
    __shared__ __align__(128) unsigned char sW[4 * 8192];
    __shared__ __align__(8) unsigned long long sBar[4];
    __shared__ uint32_t sSrc[EDGE_UNITS];
    __shared__ uint16_t sByt[EDGE_UNITS];
    __shared__ int sIdx[3 * 64];
    __shared__ float sEo[64 * 64];      // e-MLP LN output (edge-major), same-thread RW

    const int tid = threadIdx.x;
    const int lane = tid & 31, warp = tid >> 5;
    const int q = lane & 3, rloc = lane >> 2;
    const int rA = warp * 16 + rloc, rB = rA + 8;
    const int e0 = blockIdx.x * 64;

    int* srcs = sIdx; int* tgts = sIdx + 64; int* ebs = sIdx + 128;
    if (tid < 64) {
        int s = ei[e0 + tid];
        int t = ei[N_EDGES + e0 + tid];
        srcs[tid] = s; tgts[tid] = t; ebs[tid] = batch[s];
    }
    uint32_t mb = smem_u32(sBar);
    if (tid == 0) {
        for (int s = 0; s < 4; s++) MBAR_INIT(mb + s * 8u, 1);
        const int LU[8]  = {13, 8, 8, 8, 13, 8, 8, 8};
        const int LPB[8] = {4096, 4096, 4096, 2048, 4096, 4096, 4096, 2048};
        uint32_t off = 0; int uu = 0;
        for (int l = 0; l < 8; l++)
            for (int t = 0; t < LU[l]; t++) {
                sSrc[uu] = off; sByt[uu] = (uint16_t)(2 * LPB[l]);
                off += 2 * LPB[l]; uu++;
            }
    }
    __syncthreads();

    Pipe p; p.swaddr = smem_u32(sW); p.mbar = mb; p.srcOff = sSrc; p.byt = sByt;
    p.base = g_wimg; p.nU = EDGE_UNITS; p.u = 0; p.leader = (tid == 0);
    pipe_issue(p, 0); pipe_issue(p, 1); pipe_issue(p, 2);

    float acc[16][4];
    uint32_t Ahi[8][4];

    const float* B1[2] = {eb1, ab1};
    const float* BH[2] = {ebh, abh};
    const float* B2[2] = {eb2, ab2};

    for (int mlp = 0; mlp < 2; mlp++) {
        zero_acc(acc, 16);
        for (int t = 0; t < 13; t++) {
            uint32_t ah4[4];
            int c0 = 16 * t + 2 * q;
            float2 f0 = *(const float2*)eptr(c0,     rA, x, eattr, u, srcs, tgts, ebs, e0);
            float2 f1 = *(const float2*)eptr(c0,     rB, x, eattr, u, srcs, tgts, ebs, e0);
            float2 f2 = *(const float2*)eptr(c0 + 8, rA, x, eattr, u, srcs, tgts, ebs, e0);
            float2 f3 = *(const float2*)eptr(c0 + 8, rB, x, eattr, u, srcs, tgts, ebs, e0);
            ah4[0] = packh2(f0.x, f0.y);
            ah4[1] = packh2(f1.x, f1.y);
            ah4[2] = packh2(f2.x, f2.y);
            ah4[3] = packh2(f3.x, f3.y);
            uint32_t st = pipe_acquire(p);
            mma_tile<128>(acc, ah4, st, lane);
        }
        epi_relu128(acc, B1[mlp], Ahi, q);

        for (int hl = 0; hl < 2; hl++) {
            zero_acc(acc, 16);
            for (int t = 0; t < 8; t++) {
                uint32_t st = pipe_acquire(p);
                mma_tile<128>(acc, Ahi[t], st, lane);
            }
            epi_relu128(acc, BH[mlp] + hl * 128, Ahi, q);
        }

        zero_acc(acc, 8);
        for (int t = 0; t < 8; t++) {
            uint32_t st = pipe_acquire(p);
            mma_tile<64>(acc, Ahi[t], st, lane);
        }
        float vv[8][4], muA, rsA, muB, rsB;
        ln_stats(acc, B2[mlp], q, vv, muA, rsA, muB, rsB);
        if (mlp == 0) {
#pragma unroll
            for (int j = 0; j < 8; j++) {
                int c = 8 * j + 2 * q;
                float2 gm = *(const float2*)(eg + c);
                float2 bt = *(const float2*)(ebt + c);
                sEo[rA * 64 + c]     = (vv[j][0] - muA) * rsA * gm.x + bt.x;
                sEo[rA * 64 + c + 1] = (vv[j][1] - muA) * rsA * gm.y + bt.y;
                sEo[rB * 64 + c]     = (vv[j][2] - muB) * rsB * gm.x + bt.x;
                sEo[rB * 64 + c + 1] = (vv[j][3] - muB) * rsB * gm.y + bt.y;
            }
        } else {
            float* rowP_A = g_agg + (size_t)tgts[rA] * 64;
            float* rowP_B = g_agg + (size_t)tgts[rB] * 64;
#pragma unroll
            for (int j = 0; j < 8; j++) {
                int c = 8 * j + 2 * q;
                float2 gm = *(const float2*)(ag + c);
                float2 bt = *(const float2*)(abt + c);
                float a0 = (vv[j][0] - muA) * rsA * gm.x + bt.x;
                float a1 = (vv[j][1] - muA) * rsA * gm.y + bt.y;
                float a2 = (vv[j][2] - muB) * rsB * gm.x + bt.x;
                float a3 = (vv[j][3] - muB) * rsB * gm.y + bt.y;
                red2(rowP_A + c, sEo[rA * 64 + c]     * fast_sigmoid(a0),
                                 sEo[rA * 64 + c + 1] * fast_sigmoid(a1));
                red2(rowP_B + c, sEo[rB * 64 + c]     * fast_sigmoid(a2),
                                 sEo[rB * 64 + c + 1] * fast_sigmoid(a3));
            }
        }
    }
}

// ---------------------------------------------------------------------------
// node kernel: 128 threads, 64 nodes/CTA, 4 CTAs/SM
// ---------------------------------------------------------------------------
__device__ __forceinline__ const float* nptr(int c, int n, int bt,
    const float* __restrict__ x, const float* __restrict__ u) {
    if (c < 64)  return x + (size_t)n * 64 + c;
    if (c < 128) return g_agg + (size_t)n * 64 + (c - 64);
    return u + (size_t)bt * 16 + (c - 128);
}

__global__ void __launch_bounds__(BLK, 4) node_kernel(
    const float* __restrict__ x, const float* __restrict__ u, const int* __restrict__ batch,
    const float* __restrict__ nb1, const float* __restrict__ nbh, const float* __restrict__ nb2,
    const float* __restrict__ ng,  const float* __restrict__ nbt,
    float* __restrict__ out)
{
    __shared__ __align__(128) unsigned char sW[4 * 8192];
    __shared__ __align__(8) unsigned long long sBar[4];
    __shared__ uint32_t sSrc[NODE_UNITS];
    __shared__ uint16_t sByt[NODE_UNITS];
    __shared__ int sBt[64];

    const int tid = threadIdx.x;
    const int lane = tid & 31, warp = tid >> 5;
    const int q = lane & 3, rloc = lane >> 2;
    const int rA = warp * 16 + rloc, rB = rA + 8;
    const int n0 = blockIdx.x * 64;

    if (tid < 64) {
        int n = n0 + tid;
        sBt[tid] = (n < N_NODES) ? batch[n] : 0;
    }
    uint32_t mb = smem_u32(sBar);
    if (tid == 0) {
        for (int s = 0; s < 4; s++) MBAR_INIT(mb + s * 8u, 1);
        const int LU[4]  = {9, 8, 8, 8};
        const int LPB[4] = {4096, 4096, 4096, 2048};
        uint32_t off = 0; int uu = 0;
        for (int l = 0; l < 4; l++)
            for (int t = 0; t < LU[l]; t++) {
                sSrc[uu] = off; sByt[uu] = (uint16_t)(2 * LPB[l]);
                off += 2 * LPB[l]; uu++;
            }
    }
    __syncthreads();

    Pipe p; p.swaddr = smem_u32(sW); p.mbar = mb; p.srcOff = sSrc; p.byt = sByt;
    p.base = g_wimg + NODE_BASE; p.nU = NODE_UNITS; p.u = 0; p.leader = (tid == 0);
    pipe_issue(p, 0); pipe_issue(p, 1); pipe_issue(p, 2);

    const int nA = (n0 + rA < N_NODES) ? n0 + rA : N_NODES - 1;
    const int nB = (n0 + rB < N_NODES) ? n0 + rB : N_NODES - 1;
    const int btA = sBt[rA], btB = sBt[rB];

    float acc[16][4];
    uint32_t Ahi[8][4];

    zero_acc(acc, 16);
    for (int t = 0; t < 9; t++) {
        uint32_t ah4[4];
        int c0 = 16 * t + 2 * q;
        float2 f0 = *(const float2*)nptr(c0,     nA, btA, x, u);
        float2 f1 = *(const float2*)nptr(c0,     nB, btB, x, u);
        float2 f2 = *(const float2*)nptr(c0 + 8, nA, btA, x, u);
        float2 f3 = *(const float2*)nptr(c0 + 8, nB, btB, x, u);
        ah4[0] = packh2(f0.x, f0.y);
        ah4[1] = packh2(f1.x, f1.y);
        ah4[2] = packh2(f2.x, f2.y);
        ah4[3] = packh2(f3.x, f3.y);
        uint32_t st = pipe_acquire(p);
        mma_tile<128>(acc, ah4, st, lane);
    }
    epi_relu128(acc, nb1, Ahi, q);

    for (int hl = 0; hl < 2; hl++) {
        zero_acc(acc, 16);
        for (int t = 0; t < 8; t++) {
            uint32_t st = pipe_acquire(p);
            mma_tile<128>(acc, Ahi[t], st, lane);
        }
        epi_relu128(acc, nbh + hl * 128, Ahi, q);
    }

    zero_acc(acc, 8);
    for (int t = 0; t < 8; t++) {
        uint32_t st = pipe_acquire(p);
        mma_tile<64>(acc, Ahi[t], st, lane);
    }
    float vv[8][4], muA, rsA, muB, rsB;
    ln_stats(acc, nb2, q, vv, muA, rsA, muB, rsB);

    const bool vA = (n0 + rA < N_NODES), vB = (n0 + rB < N_NODES);
#pragma unroll
    for (int j = 0; j < 8; j++) {
        int c = 8 * j + 2 * q;
        float2 gm = *(const float2*)(ng + c);
        float2 bt = *(const float2*)(nbt + c);
        if (vA) {
            float2 o; o.x = (vv[j][0] - muA) * rsA * gm.x + bt.x;
            o.y = (vv[j][1] - muA) * rsA * gm.y + bt.y;
            *(float2*)(out + (size_t)(n0 + rA) * 64 + c) = o;
        }
        if (vB) {
            float2 o; o.x = (vv[j][2] - muB) * rsB * gm.x + bt.x;
            o.y = (vv[j][3] - muB) * rsB * gm.y + bt.y;
            *(float2*)(out + (size_t)(n0 + rB) * 64 + c) = o;
        }
    }
}

// ---------------------------------------------------------------------------
extern "C" void kernel_launch(void* const* d_in, const int* in_sizes, int n_in,
                              void* d_out, int out_size)
{
    const float* x     = (const float*)d_in[0];
    const float* eattr = (const float*)d_in[1];
    const float* u     = (const float*)d_in[2];
    const int*   ei    = (const int*)d_in[3];
    const int*   batch = (const int*)d_in[4];
    const float* ew1 = (const float*)d_in[5],  *eb1 = (const float*)d_in[6];
    const float* ewh = (const float*)d_in[7],  *ebh = (const float*)d_in[8];
    const float* ew2 = (const float*)d_in[9],  *eb2 = (const float*)d_in[10];
    const float* eg  = (const float*)d_in[11], *ebt = (const float*)d_in[12];
    const float* aw1 = (const float*)d_in[13], *ab1 = (const float*)d_in[14];
    const float* awh = (const float*)d_in[15], *abh = (const float*)d_in[16];
    const float* aw2 = (const float*)d_in[17], *ab2 = (const float*)d_in[18];
    const float* ag  = (const float*)d_in[19], *abt = (const float*)d_in[20];
    const float* nw1 = (const float*)d_in[21], *nb1 = (const float*)d_in[22];
    const float* nwh = (const float*)d_in[23], *nbh = (const float*)d_in[24];
    const float* nw2 = (const float*)d_in[25], *nb2 = (const float*)d_in[26];
    const float* ng  = (const float*)d_in[27], *nbt = (const float*)d_in[28];
    float* out = (float*)d_out;
    (void)in_sizes; (void)n_in; (void)out_size;

    void* aggp = nullptr;
    cudaGetSymbolAddress(&aggp, g_agg);
    cudaMemsetAsync(aggp, 0, sizeof(float) * (size_t)N_NODES * 64, 0);

    prep_kernel<<<(194560 + 255) / 256, 256>>>(ew1, ewh, ew2, aw1, awh, aw2, nw1, nwh, nw2);

    edge_kernel<<<N_EDGES / 64, BLK>>>(
        x, eattr, u, ei, batch,
        eb1, ebh, eb2, eg, ebt,
        ab1, abh, ab2, ag, abt);

    node_kernel<<<(N_NODES + 63) / 64, BLK>>>(
        x, u, batch, nb1, nbh, nb2, ng, nbt, out);
}